// round 13
// baseline (speedup 1.0000x reference)
#include <cuda_runtime.h>
#include <cuda_fp16.h>
#include <cstdint>

#define B_DIM 512
#define T_DIM 128
#define D_DIM 300
#define DPAD  320
#define H_DIM 1024
#define NCOL  4096

typedef uint32_t u32;

// ------------------------------------------------------------------
// Persistent device buffers
// ------------------------------------------------------------------
__device__ __align__(16) __half g_x[(size_t)B_DIM * T_DIM * DPAD];
__device__ __align__(16) __half g_wih0[(size_t)4 * H_DIM * DPAD];
__device__ __align__(16) __half g_whh0[(size_t)4 * H_DIM * H_DIM];
__device__ __align__(16) __half g_wih1[(size_t)4 * H_DIM * H_DIM];
__device__ __align__(16) __half g_whh1[(size_t)4 * H_DIM * H_DIM];
__device__ __align__(16) __half g_h0b[2][(size_t)B_DIM * H_DIM];
__device__ __align__(16) __half g_h1b[2][(size_t)B_DIM * H_DIM];
__device__ __align__(16) float g_part[2][(size_t)B_DIM * NCOL];
__device__ __align__(16) float g_c0[(size_t)B_DIM * H_DIM];
__device__ __align__(16) float g_c1[(size_t)B_DIM * H_DIM];
__device__ __align__(16) float g_acc[(size_t)B_DIM * H_DIM];
__device__ __align__(16) float g_b0[NCOL];   // interleaved: g_b0[n] = b[(n&3)*H + (n>>2)]
__device__ __align__(16) float g_b1[NCOL];

// ------------------------------------------------------------------
// Helpers
// ------------------------------------------------------------------
__device__ __forceinline__ u32 smem_to_u32(const void* p) {
    u32 a;
    asm("{ .reg .u64 t; cvta.to.shared.u64 t, %1; cvt.u32.u64 %0, t; }" : "=r"(a) : "l"(p));
    return a;
}
__device__ __forceinline__ void cp16(u32 s, const void* g) {
    asm volatile("cp.async.cg.shared.global [%0], [%1], 16;" :: "r"(s), "l"(g));
}
__device__ __forceinline__ void mbar_init(u32 mb, u32 cnt) {
    asm volatile("mbarrier.init.shared.b64 [%0], %1;" :: "r"(mb), "r"(cnt) : "memory");
}
__device__ __forceinline__ void mbar_arrive(u32 mb) {
    asm volatile("mbarrier.arrive.shared.b64 _, [%0];" :: "r"(mb) : "memory");
}
__device__ __forceinline__ void cp_arrive_noinc(u32 mb) {
    asm volatile("cp.async.mbarrier.arrive.noinc.shared.b64 [%0];" :: "r"(mb) : "memory");
}
__device__ __forceinline__ void mbar_wait(u32 mb, u32 parity) {
    u32 done;
    asm volatile("{\n\t.reg .pred p;\n\t"
        "mbarrier.try_wait.parity.acquire.cta.shared::cta.b64 p, [%1], %2;\n\t"
        "selp.b32 %0, 1, 0, p;\n\t}" : "=r"(done) : "r"(mb), "r"(parity) : "memory");
    if (!done) {
        asm volatile("{\n\t.reg .pred P1;\n\t"
            "WAIT_LOOP_%=:\n\t"
            "mbarrier.try_wait.parity.acquire.cta.shared::cta.b64 P1, [%0], %1, 0x989680;\n\t"
            "@P1 bra.uni WAIT_DONE_%=;\n\t"
            "bra.uni WAIT_LOOP_%=;\n\t"
            "WAIT_DONE_%=:\n\t}" :: "r"(mb), "r"(parity) : "memory");
    }
}
__device__ __forceinline__ void ldsm4(u32 addr, u32* r) {
    asm volatile("ldmatrix.sync.aligned.m8n8.x4.shared.b16 {%0,%1,%2,%3}, [%4];"
                 : "=r"(r[0]), "=r"(r[1]), "=r"(r[2]), "=r"(r[3]) : "r"(addr));
}
__device__ __forceinline__ void mma_f16(float* d, const u32* a, u32 b0, u32 b1) {
    asm volatile("mma.sync.aligned.m16n8k16.row.col.f32.f16.f16.f32 "
                 "{%0,%1,%2,%3}, {%4,%5,%6,%7}, {%8,%9}, {%0,%1,%2,%3};"
                 : "+f"(d[0]), "+f"(d[1]), "+f"(d[2]), "+f"(d[3])
                 : "r"(a[0]), "r"(a[1]), "r"(a[2]), "r"(a[3]), "r"(b0), "r"(b1));
}
__device__ __forceinline__ u32 swz(u32 row, u32 q) {
    return row * 128u + ((q ^ (row & 7u)) << 4);
}
__device__ __forceinline__ float sigf(float x) { return __fdividef(1.0f, 1.0f + __expf(-x)); }
__device__ __forceinline__ float tanhf_(float x) {
    return 1.0f - 2.0f * __fdividef(1.0f, 1.0f + __expf(2.0f * x));
}

#define TILE_B   16384          // 128 x 64 fp16
#define BUF_B    (2 * TILE_B)   // A, W
#define N_STAGE  3
#define SMEM_TOT (1024 + N_STAGE * BUF_B)  // 99328 -> 2 CTAs/SM

#define NTHR 288                // 8 consumer warps + 1 producer warp

// ------------------------------------------------------------------
// Warp-specialized fused GEMM + LSTM-cell step kernel.
// One job = one 128x128 tile. Warps 0-7: consumers (2M x 4N, 64x32 each).
// Warp 8: producer — owns all cp.async, runs ahead via empty[] waits.
// mode grids (groups of 128): L0[s_l0], L1B[s_l1b], L1A[s_l1a].
// type 0 = L1B (h1@Whh1 + part -> cell1), 1 = L1A (h0@Wih1 -> part),
// type 2 = L0 (x@Wih0 + h0@Whh0 -> cell0).
// ------------------------------------------------------------------
__global__ void __launch_bounds__(NTHR, 2)
lstm_step(int s_l0, int s_l1b, int s_l1a) {
    extern __shared__ __align__(16) char smem[];
    const u32 sbase = smem_to_u32(smem);
    const u32 sb = sbase + 1024;
    const int tid = threadIdx.x;
    const int lane = tid & 31;
    const int wid = tid >> 5;

    // job decode: groups of 128 blocks, order L0, L1B, L1A (longest first)
    const int g = blockIdx.x >> 7;
    const int jb = blockIdx.x & 127;
    int type = 2, step = 0;
    {
        int k = 0;
        if (s_l0 >= 0)  { if (g == k) { type = 2; step = s_l0; }  k++; }
        if (s_l1b >= 0) { if (g == k) { type = 0; step = s_l1b; } k++; }
        if (s_l1a >= 0) { if (g == k) { type = 1; step = s_l1a; } k++; }
    }
    const int u0 = (jb & 31) * 32;    // unit tile (32 units = 128 cols)
    const int m0 = (jb >> 5) * 128;   // batch tile

    if (tid == 0) {
#pragma unroll
        for (int s = 0; s < N_STAGE; s++) {
            mbar_init(sbase + 32 + s * 8, 32);    // full: producer warp arrivals
            mbar_init(sbase + 64 + s * 8, 256);   // empty: consumer arrivals
        }
    }
    __syncthreads();

    int nc0, NC;
    if (type == 2)      { nc0 = DPAD / 64; NC = nc0 + 16; }   // 5, 21
    else                { nc0 = 16;        NC = 16; }

    if (wid == 8) {
        // ======================= PRODUCER WARP =======================
        // lane handles A rows 4*lane..4*lane+3 and W rows 4*lane..4*lane+3
        const int r0 = lane * 4;
        const __half *paA[2][4];   // [segment][row]
        const __half *paW[2][4];
#pragma unroll
        for (int rr = 0; rr < 4; rr++) {
            const int r = r0 + rr;
            const int wrow = (r & 3) * H_DIM + u0 + (r >> 2);
            if (type == 2) {
                paA[0][rr] = g_x + (size_t)(m0 + r) * (T_DIM * DPAD) + (size_t)step * DPAD;
                paW[0][rr] = g_wih0 + (size_t)wrow * DPAD;
                paA[1][rr] = g_h0b[(step - 1) & 1] + (size_t)(m0 + r) * H_DIM;
                paW[1][rr] = g_whh0 + (size_t)wrow * H_DIM;
            } else if (type == 1) {
                paA[0][rr] = g_h0b[step & 1] + (size_t)(m0 + r) * H_DIM;
                paW[0][rr] = g_wih1 + (size_t)wrow * H_DIM;
                paA[1][rr] = paA[0][rr]; paW[1][rr] = paW[0][rr];
            } else {
                paA[0][rr] = g_h1b[(step - 1) & 1] + (size_t)(m0 + r) * H_DIM;
                paW[0][rr] = g_whh1 + (size_t)wrow * H_DIM;
                paA[1][rr] = paA[0][rr]; paW[1][rr] = paW[0][rr];
            }
        }
        for (int c = 0; c < NC; c++) {
            if (c >= N_STAGE)
                mbar_wait(sbase + 64 + (u32)(c % N_STAGE) * 8,
                          (u32)(((c / N_STAGE) - 1) & 1));
            const int sg = (c < nc0) ? 0 : 1;
            const int k0 = ((c < nc0) ? c : (c - nc0)) * 64;
            const u32 d = sb + (u32)(c % N_STAGE) * BUF_B;
#pragma unroll
            for (int rr = 0; rr < 4; rr++) {
                const int r = r0 + rr;
                const __half* pa = paA[sg][rr] + k0;
                const __half* pw = paW[sg][rr] + k0;
                const u32 rowoff = (u32)r * 128u;
                const u32 x7 = ((u32)r & 7u);
#pragma unroll
                for (int q = 0; q < 8; q++) {
                    const u32 so = rowoff + (((u32)q ^ x7) << 4);
                    cp16(d + so, pa + q * 8);
                    cp16(d + TILE_B + so, pw + q * 8);
                }
            }
            cp_arrive_noinc(sbase + 32 + (u32)(c % N_STAGE) * 8);
        }
        return;
    }

    // ======================= CONSUMER WARPS =======================
    const int wm = wid >> 2;          // 0..1 -> 64 rows
    const int wn = wid & 3;           // 0..3 -> 32 cols

    float acc[4][4][4];
#pragma unroll
    for (int mi = 0; mi < 4; mi++)
#pragma unroll
        for (int nf = 0; nf < 4; nf++)
#pragma unroll
            for (int q = 0; q < 4; q++) acc[mi][nf][q] = 0.0f;

    for (int c = 0; c < NC; c++) {
        mbar_wait(sbase + 32 + (u32)(c % N_STAGE) * 8, (u32)((c / N_STAGE) & 1));

        const u32 bA = sb + (u32)(c % N_STAGE) * BUF_B;
        const u32 bW = bA + TILE_B;
#pragma unroll
        for (int kk = 0; kk < 4; kk++) {
            u32 av[4][4], wv[2][4];
            const u32 aq = 2 * kk + (lane >> 4);
#pragma unroll
            for (int mi = 0; mi < 4; mi++) {
                const u32 row = wm * 64 + mi * 16 + (lane & 15);
                ldsm4(bA + swz(row, aq), av[mi]);
            }
            const u32 wq = 2 * kk + ((lane >> 3) & 1);
#pragma unroll
            for (int nf2 = 0; nf2 < 2; nf2++) {
                const u32 row = wn * 32 + nf2 * 16 + (lane & 7) + ((lane >> 4) << 3);
                ldsm4(bW + swz(row, wq), wv[nf2]);
            }
#pragma unroll
            for (int mi = 0; mi < 4; mi++)
#pragma unroll
                for (int nf = 0; nf < 4; nf++) {
                    const u32* W = wv[nf >> 1] + (nf & 1) * 2;
                    mma_f16(acc[mi][nf], av[mi], W[0], W[1]);
                }
        }
        mbar_arrive(sbase + 64 + (u32)(c % N_STAGE) * 8);
    }

    // ---------------- epilogues ----------------
    if (type == 1) {
        float* outp = g_part[step & 1];
#pragma unroll
        for (int mi = 0; mi < 4; mi++)
#pragma unroll
            for (int nf = 0; nf < 4; nf++) {
                const int row0 = m0 + wm * 64 + mi * 16 + (lane >> 2);
                const int col = u0 * 4 + wn * 32 + nf * 8 + 2 * (lane & 3);
                *(float2*)(outp + (size_t)row0 * NCOL + col) =
                    make_float2(acc[mi][nf][0], acc[mi][nf][1]);
                *(float2*)(outp + (size_t)(row0 + 8) * NCOL + col) =
                    make_float2(acc[mi][nf][2], acc[mi][nf][3]);
            }
        return;
    }

    float* cmem = (type == 0) ? g_c1 : g_c0;
    __half* hout = (type == 0) ? g_h1b[step & 1] : g_h0b[step & 1];
    const float* extra = (type == 0) ? g_part[step & 1] : nullptr;
    const float* gb = (type == 0) ? g_b1 : g_b0;
    const bool owner = ((lane & 1) == 0);
    const int cc = 2 * (lane & 3);

#pragma unroll
    for (int mi = 0; mi < 4; mi++)
#pragma unroll
        for (int nf = 0; nf < 4; nf++) {
            float v0 = acc[mi][nf][0], v1 = acc[mi][nf][1];
            float v2 = acc[mi][nf][2], v3 = acc[mi][nf][3];
            const float p0 = __shfl_xor_sync(0xffffffffu, v0, 1);
            const float p1 = __shfl_xor_sync(0xffffffffu, v1, 1);
            const float p2 = __shfl_xor_sync(0xffffffffu, v2, 1);
            const float p3 = __shfl_xor_sync(0xffffffffu, v3, 1);
            if (owner) {
                const int nl = wn * 32 + nf * 8 + cc;
                const int ucol = u0 + (nl >> 2);
                const float4 bv = *(const float4*)(gb + u0 * 4 + nl);
                const int rowa = m0 + wm * 64 + mi * 16 + (lane >> 2);
#pragma unroll
                for (int rh = 0; rh < 2; rh++) {
                    const int b = rowa + rh * 8;
                    float iv = (rh ? v2 : v0) + bv.x;
                    float fv = (rh ? v3 : v1) + bv.y;
                    float gv = (rh ? p2 : p0) + bv.z;
                    float ov = (rh ? p3 : p1) + bv.w;
                    if (extra) {
                        const float2 e01 = *(const float2*)(extra + (size_t)b * NCOL + u0 * 4 + nl);
                        const float2 e23 = *(const float2*)(extra + (size_t)b * NCOL + u0 * 4 + nl + 2);
                        iv += e01.x; fv += e01.y; gv += e23.x; ov += e23.y;
                    }
                    const size_t ci = (size_t)b * H_DIM + ucol;
                    const float cold = cmem[ci];
                    const float cn = sigf(fv) * cold + sigf(iv) * tanhf_(gv);
                    const float hn = sigf(ov) * tanhf_(cn);
                    cmem[ci] = cn;
                    hout[ci] = __float2half(hn);
                    if (type == 0) g_acc[ci] += hn;
                }
            }
        }
}

// ------------------------------------------------------------------
__global__ void prolog_k(const float* __restrict__ x,
                         const float* __restrict__ Wih0, const float* __restrict__ Whh0,
                         const float* __restrict__ Wih1, const float* __restrict__ Whh1,
                         const float* __restrict__ bih0, const float* __restrict__ bhh0,
                         const float* __restrict__ bih1, const float* __restrict__ bhh1) {
    const size_t stride = (size_t)gridDim.x * blockDim.x;
    const size_t tid0 = (size_t)blockIdx.x * blockDim.x + threadIdx.x;
    for (size_t i = tid0; i < NCOL; i += stride) {
        const size_t src = (i & 3) * H_DIM + (i >> 2);
        g_b0[i] = bih0[src] + bhh0[src];
        g_b1[i] = bih1[src] + bhh1[src];
    }
    {
        const size_t n = (size_t)4 * H_DIM * DPAD;
        for (size_t i = tid0; i < n; i += stride) {
            const size_t row = i / DPAD;
            const int k = (int)(i % DPAD);
            g_wih0[i] = __float2half((k < D_DIM) ? Wih0[row * D_DIM + k] : 0.0f);
        }
    }
    {
        const size_t n = (size_t)4 * H_DIM * H_DIM;
        for (size_t i = tid0; i < n; i += stride) {
            g_whh0[i] = __float2half(Whh0[i]);
            g_wih1[i] = __float2half(Wih1[i]);
            g_whh1[i] = __float2half(Whh1[i]);
        }
    }
    {
        const size_t n = (size_t)B_DIM * T_DIM * DPAD;
        for (size_t i = tid0; i < n; i += stride) {
            const size_t bt = i / DPAD;
            const int k = (int)(i % DPAD);
            g_x[i] = __float2half((k < D_DIM) ? x[bt * D_DIM + k] : 0.0f);
        }
    }
    {
        const size_t n = (size_t)B_DIM * H_DIM;
        for (size_t i = tid0; i < n; i += stride) {
            g_h0b[0][i] = __float2half(0.0f);
            g_h0b[1][i] = __float2half(0.0f);
            g_h1b[0][i] = __float2half(0.0f);
            g_h1b[1][i] = __float2half(0.0f);
            g_c0[i] = 0.0f; g_c1[i] = 0.0f; g_acc[i] = 0.0f;
        }
    }
}

__global__ void finalize_k(const float* __restrict__ Wdec,
                           const float* __restrict__ bdec, float* __restrict__ out) {
    const int b = blockIdx.x;
    const int tid = threadIdx.x;  // 128
    float p = 0.0f;
    for (int u = tid; u < H_DIM; u += 128)
        p += g_acc[(size_t)b * H_DIM + u] * Wdec[u];
#pragma unroll
    for (int o = 16; o; o >>= 1) p += __shfl_down_sync(0xffffffffu, p, o);
    __shared__ float red[4];
    if ((tid & 31) == 0) red[tid >> 5] = p;
    __syncthreads();
    if (tid == 0)
        out[b] = (red[0] + red[1] + red[2] + red[3]) * (1.0f / (float)T_DIM) + bdec[0];
}

// ------------------------------------------------------------------
extern "C" void kernel_launch(void* const* d_in, const int* in_sizes, int n_in,
                              void* d_out, int out_size) {
    const float* x    = (const float*)d_in[0];
    const float* Wih0 = (const float*)d_in[1];
    const float* Whh0 = (const float*)d_in[2];
    const float* bih0 = (const float*)d_in[3];
    const float* bhh0 = (const float*)d_in[4];
    const float* Wih1 = (const float*)d_in[5];
    const float* Whh1 = (const float*)d_in[6];
    const float* bih1 = (const float*)d_in[7];
    const float* bhh1 = (const float*)d_in[8];
    const float* Wdec = (const float*)d_in[9];
    const float* bdec = (const float*)d_in[10];
    float* out = (float*)d_out;

    cudaFuncSetAttribute(lstm_step, cudaFuncAttributeMaxDynamicSharedMemorySize, SMEM_TOT);

    prolog_k<<<2048, 256>>>(x, Wih0, Whh0, Wih1, Whh1, bih0, bhh0, bih1, bhh1);

    // schedule: launch(t) = { L0[t+1], L1B[t-1], L1A[t] }, 128 jobs per type
    lstm_step<<<128, NTHR, SMEM_TOT>>>(0, -1, -1);           // L0[0]
    lstm_step<<<256, NTHR, SMEM_TOT>>>(1, -1, 0);            // L0[1], L1A[0]
    for (int t = 1; t <= T_DIM - 2; ++t)                     // t = 1..126
        lstm_step<<<384, NTHR, SMEM_TOT>>>(t + 1, t - 1, t);
    lstm_step<<<256, NTHR, SMEM_TOT>>>(-1, T_DIM - 2, T_DIM - 1);
    lstm_step<<<128, NTHR, SMEM_TOT>>>(-1, T_DIM - 1, -1);

    finalize_k<<<B_DIM, 128>>>(Wdec, bdec, out);
}

// round 14
// speedup vs baseline: 1.3319x; 1.3319x over previous
#include <cuda_runtime.h>
#include <cuda_fp16.h>
#include <cstdint>

#define B_DIM 512
#define T_DIM 128
#define D_DIM 300
#define DPAD  320
#define H_DIM 1024
#define NCOL  4096

typedef uint32_t u32;

// ------------------------------------------------------------------
// Persistent device buffers
// ------------------------------------------------------------------
__device__ __align__(16) __half g_x[(size_t)B_DIM * T_DIM * DPAD];
__device__ __align__(16) __half g_wih0[(size_t)4 * H_DIM * DPAD];
__device__ __align__(16) __half g_whh0[(size_t)4 * H_DIM * H_DIM];
__device__ __align__(16) __half g_wih1[(size_t)4 * H_DIM * H_DIM];
__device__ __align__(16) __half g_whh1[(size_t)4 * H_DIM * H_DIM];
__device__ __align__(16) __half g_h0b[2][(size_t)B_DIM * H_DIM];
__device__ __align__(16) __half g_h1b[2][(size_t)B_DIM * H_DIM];
__device__ __align__(16) __half g_px[(size_t)B_DIM * T_DIM * NCOL];   // x@Wih0, interleaved cols
__device__ __align__(16) __half g_part[2][(size_t)B_DIM * NCOL];      // h0@Wih1 partials
__device__ __align__(16) float g_c0[(size_t)B_DIM * H_DIM];
__device__ __align__(16) float g_c1[(size_t)B_DIM * H_DIM];
__device__ __align__(16) float g_acc[(size_t)B_DIM * H_DIM];
__device__ __align__(16) float g_b0[NCOL];   // interleaved: g_b0[n] = b[(n&3)*H + (n>>2)]
__device__ __align__(16) float g_b1[NCOL];

// ------------------------------------------------------------------
// Helpers
// ------------------------------------------------------------------
__device__ __forceinline__ u32 smem_to_u32(const void* p) {
    u32 a;
    asm("{ .reg .u64 t; cvta.to.shared.u64 t, %1; cvt.u32.u64 %0, t; }" : "=r"(a) : "l"(p));
    return a;
}
__device__ __forceinline__ void cp16(u32 s, const void* g) {
    asm volatile("cp.async.cg.shared.global [%0], [%1], 16;" :: "r"(s), "l"(g));
}
__device__ __forceinline__ void mbar_init(u32 mb, u32 cnt) {
    asm volatile("mbarrier.init.shared.b64 [%0], %1;" :: "r"(mb), "r"(cnt) : "memory");
}
__device__ __forceinline__ void mbar_arrive(u32 mb) {
    asm volatile("mbarrier.arrive.shared.b64 _, [%0];" :: "r"(mb) : "memory");
}
__device__ __forceinline__ void cp_arrive_noinc(u32 mb) {
    asm volatile("cp.async.mbarrier.arrive.noinc.shared.b64 [%0];" :: "r"(mb) : "memory");
}
__device__ __forceinline__ void mbar_wait(u32 mb, u32 parity) {
    u32 done;
    asm volatile("{\n\t.reg .pred p;\n\t"
        "mbarrier.try_wait.parity.acquire.cta.shared::cta.b64 p, [%1], %2;\n\t"
        "selp.b32 %0, 1, 0, p;\n\t}" : "=r"(done) : "r"(mb), "r"(parity) : "memory");
    if (!done) {
        asm volatile("{\n\t.reg .pred P1;\n\t"
            "WAIT_LOOP_%=:\n\t"
            "mbarrier.try_wait.parity.acquire.cta.shared::cta.b64 P1, [%0], %1, 0x989680;\n\t"
            "@P1 bra.uni WAIT_DONE_%=;\n\t"
            "bra.uni WAIT_LOOP_%=;\n\t"
            "WAIT_DONE_%=:\n\t}" :: "r"(mb), "r"(parity) : "memory");
    }
}
__device__ __forceinline__ void ldsm4(u32 addr, u32* r) {
    asm volatile("ldmatrix.sync.aligned.m8n8.x4.shared.b16 {%0,%1,%2,%3}, [%4];"
                 : "=r"(r[0]), "=r"(r[1]), "=r"(r[2]), "=r"(r[3]) : "r"(addr));
}
__device__ __forceinline__ void mma_f16(float* d, const u32* a, u32 b0, u32 b1) {
    asm volatile("mma.sync.aligned.m16n8k16.row.col.f32.f16.f16.f32 "
                 "{%0,%1,%2,%3}, {%4,%5,%6,%7}, {%8,%9}, {%0,%1,%2,%3};"
                 : "+f"(d[0]), "+f"(d[1]), "+f"(d[2]), "+f"(d[3])
                 : "r"(a[0]), "r"(a[1]), "r"(a[2]), "r"(a[3]), "r"(b0), "r"(b1));
}
__device__ __forceinline__ u32 swz(u32 row, u32 q) {
    return row * 128u + ((q ^ (row & 7u)) << 4);
}
__device__ __forceinline__ float sigf(float x) { return __fdividef(1.0f, 1.0f + __expf(-x)); }
__device__ __forceinline__ float tanhf_(float x) {
    return 1.0f - 2.0f * __fdividef(1.0f, 1.0f + __expf(2.0f * x));
}

#define TILE_B   16384          // 128 x 64 fp16
#define BUF_B    (2 * TILE_B)   // A, W
#define N_STAGE  3
#define SMEM_TOT (1024 + N_STAGE * BUF_B)  // 99328 -> 2 CTAs/SM

// ------------------------------------------------------------------
// Fused GEMM + LSTM-cell step kernel (one job = one 128x128 tile).
// CTA: 256 thr, 8 warps (2Mx4N), warp tile 64x32, BK=64.
// type 0 = L1B (h1@Whh1 + part -> cell1), 1 = L1A (h0@Wih1 -> part fp16),
// type 2 = L0B (h0prev@Whh0 + px -> cell0), 3 = PX (x@Wih0 -> px fp16).
// PX mode: s_l0 == -2, grid = 16384 (512 bt-tiles x 32 u-tiles), 5 chunks.
// ------------------------------------------------------------------
__global__ void __launch_bounds__(256, 2)
lstm_step(int s_l0, int s_l1b, int s_l1a) {
    extern __shared__ __align__(16) char smem[];
    const u32 sbase = smem_to_u32(smem);
    const u32 sb = sbase + 1024;
    const int tid = threadIdx.x;
    const int lane = tid & 31;
    const int wid = tid >> 5;
    const int wm = wid >> 2;
    const int wn = wid & 3;

    int type, step = 0, jb;
    if (s_l0 == -2) {
        type = 3;
        jb = blockIdx.x;              // 0..16383
    } else {
        const int g = blockIdx.x >> 7;
        jb = blockIdx.x & 127;
        type = 2;
        int k = 0;
        if (s_l0 >= 0)  { if (g == k) { type = 2; step = s_l0; }  k++; }
        if (s_l1b >= 0) { if (g == k) { type = 0; step = s_l1b; } k++; }
        if (s_l1a >= 0) { if (g == k) { type = 1; step = s_l1a; } k++; }
    }
    const int u0 = (jb & 31) * 32;
    const int m0 = (jb >> 5) * 128;   // batch tile, or bt tile for PX

    if (tid == 0) {
#pragma unroll
        for (int s = 0; s < N_STAGE; s++) {
            mbar_init(sbase + 32 + s * 8, 256);  // full: cp.async noinc arrivals
            mbar_init(sbase + 64 + s * 8, 8);    // empty: lane-0 per consumer warp
        }
    }
    __syncthreads();

    // per-thread load row
    const int r = tid >> 1;
    const int h4 = (tid & 1) * 4;
    const int wrow = (r & 3) * H_DIM + u0 + (r >> 2);

    const __half *pa0, *pw0;
    int NC;
    if (type == 3) {           // PX: rows are bt
        pa0 = g_x + (size_t)(m0 + r) * DPAD;
        pw0 = g_wih0 + (size_t)wrow * DPAD;
        NC = DPAD / 64;   // 5
    } else if (type == 2) {    // L0B
        pa0 = g_h0b[(step - 1) & 1] + (size_t)(m0 + r) * H_DIM;
        pw0 = g_whh0 + (size_t)wrow * H_DIM;
        NC = 16;
    } else if (type == 1) {    // L1A
        pa0 = g_h0b[step & 1] + (size_t)(m0 + r) * H_DIM;
        pw0 = g_wih1 + (size_t)wrow * H_DIM;
        NC = 16;
    } else {                   // L1B
        pa0 = g_h1b[(step - 1) & 1] + (size_t)(m0 + r) * H_DIM;
        pw0 = g_whh1 + (size_t)wrow * H_DIM;
        NC = 16;
    }

    float acc[4][4][4];
#pragma unroll
    for (int mi = 0; mi < 4; mi++)
#pragma unroll
        for (int nf = 0; nf < 4; nf++)
#pragma unroll
            for (int q = 0; q < 4; q++) acc[mi][nf][q] = 0.0f;

    auto produce = [&](int c) {
        const __half* pa = pa0 + c * 64;
        const __half* pw = pw0 + c * 64;
        const u32 d = sb + (u32)(c % N_STAGE) * BUF_B;
#pragma unroll
        for (int j = 0; j < 4; j++) {
            const int q = h4 + j;
            const u32 so = swz((u32)r, (u32)q);
            cp16(d + so, pa + q * 8);
            cp16(d + TILE_B + so, pw + q * 8);
        }
        cp_arrive_noinc(sbase + 32 + (u32)(c % N_STAGE) * 8);
    };

    produce(0);
    produce(1);

    for (int c = 0; c < NC; c++) {
        const int pc = c + 2;
        if (pc < NC) {
            if (pc >= N_STAGE)
                mbar_wait(sbase + 64 + (u32)(pc % N_STAGE) * 8,
                          (u32)(((pc / N_STAGE) - 1) & 1));
            produce(pc);
        }
        mbar_wait(sbase + 32 + (u32)(c % N_STAGE) * 8, (u32)((c / N_STAGE) & 1));

        const u32 bA = sb + (u32)(c % N_STAGE) * BUF_B;
        const u32 bW = bA + TILE_B;
#pragma unroll
        for (int kk = 0; kk < 4; kk++) {
            u32 av[4][4], wv[2][4];
            const u32 aq = 2 * kk + (lane >> 4);
#pragma unroll
            for (int mi = 0; mi < 4; mi++) {
                const u32 row = wm * 64 + mi * 16 + (lane & 15);
                ldsm4(bA + swz(row, aq), av[mi]);
            }
            const u32 wq = 2 * kk + ((lane >> 3) & 1);
#pragma unroll
            for (int nf2 = 0; nf2 < 2; nf2++) {
                const u32 row = wn * 32 + nf2 * 16 + (lane & 7) + ((lane >> 4) << 3);
                ldsm4(bW + swz(row, wq), wv[nf2]);
            }
#pragma unroll
            for (int mi = 0; mi < 4; mi++)
#pragma unroll
                for (int nf = 0; nf < 4; nf++) {
                    const u32* W = wv[nf >> 1] + (nf & 1) * 2;
                    mma_f16(acc[mi][nf], av[mi], W[0], W[1]);
                }
        }
        if (lane == 0) mbar_arrive(sbase + 64 + (u32)(c % N_STAGE) * 8);
    }

    // ---------------- epilogues ----------------
    if (type == 1 || type == 3) {  // raw fp16 partial store (interleaved cols)
        __half* outp = (type == 1) ? g_part[step & 1] : g_px;
#pragma unroll
        for (int mi = 0; mi < 4; mi++)
#pragma unroll
            for (int nf = 0; nf < 4; nf++) {
                const int row0 = m0 + wm * 64 + mi * 16 + (lane >> 2);
                const int col = u0 * 4 + wn * 32 + nf * 8 + 2 * (lane & 3);
                *(__half2*)(outp + (size_t)row0 * NCOL + col) =
                    __floats2half2_rn(acc[mi][nf][0], acc[mi][nf][1]);
                *(__half2*)(outp + (size_t)(row0 + 8) * NCOL + col) =
                    __floats2half2_rn(acc[mi][nf][2], acc[mi][nf][3]);
            }
        return;
    }

    // cell epilogues (type 0: L1B, type 2: L0B)
    float* cmem = (type == 0) ? g_c1 : g_c0;
    __half* hout = (type == 0) ? g_h1b[step & 1] : g_h0b[step & 1];
    const float* gb = (type == 0) ? g_b1 : g_b0;
    // partial source: type0 -> g_part[step&1] (row stride NCOL);
    //                 type2 -> g_px + step*NCOL (row stride T*NCOL)
    const __half* ebase = (type == 0) ? g_part[step & 1]
                                      : (g_px + (size_t)step * NCOL);
    const size_t estride = (type == 0) ? (size_t)NCOL : (size_t)T_DIM * NCOL;
    const bool owner = ((lane & 1) == 0);
    const int cc = 2 * (lane & 3);

#pragma unroll
    for (int mi = 0; mi < 4; mi++)
#pragma unroll
        for (int nf = 0; nf < 4; nf++) {
            float v0 = acc[mi][nf][0], v1 = acc[mi][nf][1];
            float v2 = acc[mi][nf][2], v3 = acc[mi][nf][3];
            const float p0 = __shfl_xor_sync(0xffffffffu, v0, 1);
            const float p1 = __shfl_xor_sync(0xffffffffu, v1, 1);
            const float p2 = __shfl_xor_sync(0xffffffffu, v2, 1);
            const float p3 = __shfl_xor_sync(0xffffffffu, v3, 1);
            if (owner) {
                const int nl = wn * 32 + nf * 8 + cc;
                const int ucol = u0 + (nl >> 2);
                const float4 bv = *(const float4*)(gb + u0 * 4 + nl);
                const int rowa = m0 + wm * 64 + mi * 16 + (lane >> 2);
#pragma unroll
                for (int rh = 0; rh < 2; rh++) {
                    const int b = rowa + rh * 8;
                    float iv = (rh ? v2 : v0) + bv.x;
                    float fv = (rh ? v3 : v1) + bv.y;
                    float gv = (rh ? p2 : p0) + bv.z;
                    float ov = (rh ? p3 : p1) + bv.w;
                    {
                        const __half* ep = ebase + (size_t)b * estride + u0 * 4 + nl;
                        const __half2 e01 = *(const __half2*)(ep);
                        const __half2 e23 = *(const __half2*)(ep + 2);
                        iv += __low2float(e01);  fv += __high2float(e01);
                        gv += __low2float(e23);  ov += __high2float(e23);
                    }
                    const size_t ci = (size_t)b * H_DIM + ucol;
                    const float cold = cmem[ci];
                    const float cn = sigf(fv) * cold + sigf(iv) * tanhf_(gv);
                    const float hn = sigf(ov) * tanhf_(cn);
                    cmem[ci] = cn;
                    hout[ci] = __float2half(hn);
                    if (type == 0) g_acc[ci] += hn;
                }
            }
        }
}

// ------------------------------------------------------------------
__global__ void prolog_k(const float* __restrict__ x,
                         const float* __restrict__ Wih0, const float* __restrict__ Whh0,
                         const float* __restrict__ Wih1, const float* __restrict__ Whh1,
                         const float* __restrict__ bih0, const float* __restrict__ bhh0,
                         const float* __restrict__ bih1, const float* __restrict__ bhh1) {
    const size_t stride = (size_t)gridDim.x * blockDim.x;
    const size_t tid0 = (size_t)blockIdx.x * blockDim.x + threadIdx.x;
    for (size_t i = tid0; i < NCOL; i += stride) {
        const size_t src = (i & 3) * H_DIM + (i >> 2);
        g_b0[i] = bih0[src] + bhh0[src];
        g_b1[i] = bih1[src] + bhh1[src];
    }
    {
        const size_t n = (size_t)4 * H_DIM * DPAD;
        for (size_t i = tid0; i < n; i += stride) {
            const size_t row = i / DPAD;
            const int k = (int)(i % DPAD);
            g_wih0[i] = __float2half((k < D_DIM) ? Wih0[row * D_DIM + k] : 0.0f);
        }
    }
    {
        const size_t n = (size_t)4 * H_DIM * H_DIM;
        for (size_t i = tid0; i < n; i += stride) {
            g_whh0[i] = __float2half(Whh0[i]);
            g_wih1[i] = __float2half(Wih1[i]);
            g_whh1[i] = __float2half(Whh1[i]);
        }
    }
    {
        const size_t n = (size_t)B_DIM * T_DIM * DPAD;
        for (size_t i = tid0; i < n; i += stride) {
            const size_t bt = i / DPAD;
            const int k = (int)(i % DPAD);
            g_x[i] = __float2half((k < D_DIM) ? x[bt * D_DIM + k] : 0.0f);
        }
    }
    {
        const size_t n = (size_t)B_DIM * H_DIM;
        for (size_t i = tid0; i < n; i += stride) {
            g_h0b[0][i] = __float2half(0.0f);
            g_h0b[1][i] = __float2half(0.0f);
            g_h1b[0][i] = __float2half(0.0f);
            g_h1b[1][i] = __float2half(0.0f);
            g_c0[i] = 0.0f; g_c1[i] = 0.0f; g_acc[i] = 0.0f;
        }
    }
}

__global__ void finalize_k(const float* __restrict__ Wdec,
                           const float* __restrict__ bdec, float* __restrict__ out) {
    const int b = blockIdx.x;
    const int tid = threadIdx.x;  // 128
    float p = 0.0f;
    for (int u = tid; u < H_DIM; u += 128)
        p += g_acc[(size_t)b * H_DIM + u] * Wdec[u];
#pragma unroll
    for (int o = 16; o; o >>= 1) p += __shfl_down_sync(0xffffffffu, p, o);
    __shared__ float red[4];
    if ((tid & 31) == 0) red[tid >> 5] = p;
    __syncthreads();
    if (tid == 0)
        out[b] = (red[0] + red[1] + red[2] + red[3]) * (1.0f / (float)T_DIM) + bdec[0];
}

// ------------------------------------------------------------------
extern "C" void kernel_launch(void* const* d_in, const int* in_sizes, int n_in,
                              void* d_out, int out_size) {
    const float* x    = (const float*)d_in[0];
    const float* Wih0 = (const float*)d_in[1];
    const float* Whh0 = (const float*)d_in[2];
    const float* bih0 = (const float*)d_in[3];
    const float* bhh0 = (const float*)d_in[4];
    const float* Wih1 = (const float*)d_in[5];
    const float* Whh1 = (const float*)d_in[6];
    const float* bih1 = (const float*)d_in[7];
    const float* bhh1 = (const float*)d_in[8];
    const float* Wdec = (const float*)d_in[9];
    const float* bdec = (const float*)d_in[10];
    float* out = (float*)d_out;

    cudaFuncSetAttribute(lstm_step, cudaFuncAttributeMaxDynamicSharedMemorySize, SMEM_TOT);

    prolog_k<<<2048, 256>>>(x, Wih0, Whh0, Wih1, Whh1, bih0, bhh0, bih1, bhh1);

    // precompute px = x @ Wih0^T for all (b,t): 512 bt-tiles x 32 u-tiles
    lstm_step<<<16384, 256, SMEM_TOT>>>(-2, -1, -1);

    // schedule: launch(t) = { L0B[t+1], L1B[t-1], L1A[t] }, 128 jobs per type
    lstm_step<<<128, 256, SMEM_TOT>>>(0, -1, -1);            // L0B[0]
    lstm_step<<<256, 256, SMEM_TOT>>>(1, -1, 0);             // L0B[1], L1A[0]
    for (int t = 1; t <= T_DIM - 2; ++t)                     // t = 1..126
        lstm_step<<<384, 256, SMEM_TOT>>>(t + 1, t - 1, t);
    lstm_step<<<256, 256, SMEM_TOT>>>(-1, T_DIM - 2, T_DIM - 1);
    lstm_step<<<128, 256, SMEM_TOT>>>(-1, T_DIM - 1, -1);

    finalize_k<<<B_DIM, 128>>>(Wdec, bdec, out);
}

// round 15
// speedup vs baseline: 1.3755x; 1.0328x over previous
#include <cuda_runtime.h>
#include <cuda_fp16.h>
#include <cstdint>

#define B_DIM 512
#define T_DIM 128
#define D_DIM 300
#define DPAD  320
#define H_DIM 1024
#define NCOL  4096

typedef uint32_t u32;

// ------------------------------------------------------------------
// Persistent device buffers
// ------------------------------------------------------------------
__device__ __align__(16) __half g_x[(size_t)B_DIM * T_DIM * DPAD];
__device__ __align__(16) __half g_wih0[(size_t)4 * H_DIM * DPAD];
__device__ __align__(16) __half g_whh0[(size_t)4 * H_DIM * H_DIM];
__device__ __align__(16) __half g_wih1[(size_t)4 * H_DIM * H_DIM];
__device__ __align__(16) __half g_whh1[(size_t)4 * H_DIM * H_DIM];
__device__ __align__(16) __half g_h0b[2][(size_t)B_DIM * H_DIM];
__device__ __align__(16) __half g_h1all[(size_t)(T_DIM + 1) * B_DIM * H_DIM]; // slice t+1 = h1[t]
__device__ __align__(16) __half g_part[2][(size_t)B_DIM * NCOL];  // h0@Wih1 partials (fp16)
__device__ __align__(16) float g_c0[(size_t)B_DIM * H_DIM];
__device__ __align__(16) float g_c1[(size_t)B_DIM * H_DIM];
__device__ __align__(16) float g_b0[NCOL];   // interleaved: g_b0[n] = b[(n&3)*H + (n>>2)]
__device__ __align__(16) float g_b1[NCOL];

// ------------------------------------------------------------------
// Helpers
// ------------------------------------------------------------------
__device__ __forceinline__ u32 smem_to_u32(const void* p) {
    u32 a;
    asm("{ .reg .u64 t; cvta.to.shared.u64 t, %1; cvt.u32.u64 %0, t; }" : "=r"(a) : "l"(p));
    return a;
}
__device__ __forceinline__ void cp16(u32 s, const void* g) {
    asm volatile("cp.async.cg.shared.global [%0], [%1], 16;" :: "r"(s), "l"(g));
}
#define CP_COMMIT() asm volatile("cp.async.commit_group;" ::: "memory")
#define CP_WAIT0()  asm volatile("cp.async.wait_group 0;" ::: "memory")
__device__ __forceinline__ void mbar_init(u32 mb, u32 cnt) {
    asm volatile("mbarrier.init.shared.b64 [%0], %1;" :: "r"(mb), "r"(cnt) : "memory");
}
__device__ __forceinline__ void mbar_arrive(u32 mb) {
    asm volatile("mbarrier.arrive.shared.b64 _, [%0];" :: "r"(mb) : "memory");
}
__device__ __forceinline__ void cp_arrive_noinc(u32 mb) {
    asm volatile("cp.async.mbarrier.arrive.noinc.shared.b64 [%0];" :: "r"(mb) : "memory");
}
__device__ __forceinline__ void mbar_wait(u32 mb, u32 parity) {
    u32 done;
    asm volatile("{\n\t.reg .pred p;\n\t"
        "mbarrier.try_wait.parity.acquire.cta.shared::cta.b64 p, [%1], %2;\n\t"
        "selp.b32 %0, 1, 0, p;\n\t}" : "=r"(done) : "r"(mb), "r"(parity) : "memory");
    if (!done) {
        asm volatile("{\n\t.reg .pred P1;\n\t"
            "WAIT_LOOP_%=:\n\t"
            "mbarrier.try_wait.parity.acquire.cta.shared::cta.b64 P1, [%0], %1, 0x989680;\n\t"
            "@P1 bra.uni WAIT_DONE_%=;\n\t"
            "bra.uni WAIT_LOOP_%=;\n\t"
            "WAIT_DONE_%=:\n\t}" :: "r"(mb), "r"(parity) : "memory");
    }
}
__device__ __forceinline__ void ldsm4(u32 addr, u32* r) {
    asm volatile("ldmatrix.sync.aligned.m8n8.x4.shared.b16 {%0,%1,%2,%3}, [%4];"
                 : "=r"(r[0]), "=r"(r[1]), "=r"(r[2]), "=r"(r[3]) : "r"(addr));
}
__device__ __forceinline__ void mma_f16(float* d, const u32* a, u32 b0, u32 b1) {
    asm volatile("mma.sync.aligned.m16n8k16.row.col.f32.f16.f16.f32 "
                 "{%0,%1,%2,%3}, {%4,%5,%6,%7}, {%8,%9}, {%0,%1,%2,%3};"
                 : "+f"(d[0]), "+f"(d[1]), "+f"(d[2]), "+f"(d[3])
                 : "r"(a[0]), "r"(a[1]), "r"(a[2]), "r"(a[3]), "r"(b0), "r"(b1));
}
__device__ __forceinline__ u32 swz(u32 row, u32 q) {
    return row * 128u + ((q ^ (row & 7u)) << 4);
}
__device__ __forceinline__ float sigf(float x) { return __fdividef(1.0f, 1.0f + __expf(-x)); }
__device__ __forceinline__ float tanhf_(float x) {
    return 1.0f - 2.0f * __fdividef(1.0f, 1.0f + __expf(2.0f * x));
}

#define TILE_B   16384          // 128 x 64 fp16
#define BUF_B    (2 * TILE_B)   // A, W
#define N_STAGE  3
#define SMEM_TOT (1024 + N_STAGE * BUF_B)  // 99328 -> 2 CTAs/SM

// ------------------------------------------------------------------
// Fused GEMM + LSTM-cell step kernel (one job = one 128x128 tile).
// CTA: 256 thr, 8 warps (2Mx4N), warp tile 64x32, BK=64.
// type 0 = L1B (h1@Whh1 + part -> cell1 -> g_h1all), 1 = L1A (h0@Wih1 ->
// part fp16), 2 = L0 (x@Wih0 + h0@Whh0 -> cell0).
// All epilogue I/O is staged through SMEM and written back in 16B
// coalesced ops (the ring buffers are dead after the mainloop).
// ------------------------------------------------------------------
__global__ void __launch_bounds__(256, 2)
lstm_step(int s_l0, int s_l1b, int s_l1a) {
    extern __shared__ __align__(16) char smem[];
    const u32 sbase = smem_to_u32(smem);
    const u32 sb = sbase + 1024;
    const int tid = threadIdx.x;
    const int lane = tid & 31;
    const int wid = tid >> 5;
    const int wm = wid >> 2;
    const int wn = wid & 3;

    // job decode: groups of 128 blocks, order L0, L1B, L1A (longest first)
    const int g = blockIdx.x >> 7;
    const int jb = blockIdx.x & 127;
    int type = 2, step = 0;
    {
        int k = 0;
        if (s_l0 >= 0)  { if (g == k) { type = 2; step = s_l0; }  k++; }
        if (s_l1b >= 0) { if (g == k) { type = 0; step = s_l1b; } k++; }
        if (s_l1a >= 0) { if (g == k) { type = 1; step = s_l1a; } k++; }
    }
    const int u0 = (jb & 31) * 32;
    const int m0 = (jb >> 5) * 128;

    if (tid == 0) {
#pragma unroll
        for (int s = 0; s < N_STAGE; s++) {
            mbar_init(sbase + 32 + s * 8, 256);  // full: cp.async noinc arrivals
            mbar_init(sbase + 64 + s * 8, 8);    // empty: lane-0 per consumer warp
        }
    }
    __syncthreads();

    // per-thread load row
    const int r = tid >> 1;
    const int h4 = (tid & 1) * 4;
    const int wrow = (r & 3) * H_DIM + u0 + (r >> 2);

    const __half *pa0, *pw0, *pa1 = nullptr, *pw1 = nullptr;
    int nc0, NC;
    if (type == 2) {
        pa0 = g_x + (size_t)(m0 + r) * (T_DIM * DPAD) + (size_t)step * DPAD;
        pw0 = g_wih0 + (size_t)wrow * DPAD;
        nc0 = DPAD / 64;  // 5
        pa1 = g_h0b[(step - 1) & 1] + (size_t)(m0 + r) * H_DIM;
        pw1 = g_whh0 + (size_t)wrow * H_DIM;
        NC = nc0 + 16;    // 21
    } else if (type == 1) {
        pa0 = g_h0b[step & 1] + (size_t)(m0 + r) * H_DIM;
        pw0 = g_wih1 + (size_t)wrow * H_DIM;
        nc0 = 16; NC = 16;
    } else {
        pa0 = g_h1all + ((size_t)step * B_DIM + m0 + r) * H_DIM;  // h1[step-1] = slice step
        pw0 = g_whh1 + (size_t)wrow * H_DIM;
        nc0 = 16; NC = 16;
    }

    float acc[4][4][4];
#pragma unroll
    for (int mi = 0; mi < 4; mi++)
#pragma unroll
        for (int nf = 0; nf < 4; nf++)
#pragma unroll
            for (int q = 0; q < 4; q++) acc[mi][nf][q] = 0.0f;

    auto produce = [&](int c) {
        const __half* pa; const __half* pw; int k0;
        if (c < nc0) { pa = pa0; pw = pw0; k0 = c * 64; }
        else         { pa = pa1; pw = pw1; k0 = (c - nc0) * 64; }
        const u32 d = sb + (u32)(c % N_STAGE) * BUF_B;
#pragma unroll
        for (int j = 0; j < 4; j++) {
            const int q = h4 + j;
            const u32 so = swz((u32)r, (u32)q);
            cp16(d + so, pa + k0 + q * 8);
            cp16(d + TILE_B + so, pw + k0 + q * 8);
        }
        cp_arrive_noinc(sbase + 32 + (u32)(c % N_STAGE) * 8);
    };

    produce(0);
    produce(1);

    for (int c = 0; c < NC; c++) {
        const int pc = c + 2;
        if (pc < NC) {
            if (pc >= N_STAGE)
                mbar_wait(sbase + 64 + (u32)(pc % N_STAGE) * 8,
                          (u32)(((pc / N_STAGE) - 1) & 1));
            produce(pc);
        }
        mbar_wait(sbase + 32 + (u32)(c % N_STAGE) * 8, (u32)((c / N_STAGE) & 1));

        const u32 bA = sb + (u32)(c % N_STAGE) * BUF_B;
        const u32 bW = bA + TILE_B;
#pragma unroll
        for (int kk = 0; kk < 4; kk++) {
            u32 av[4][4], wv[2][4];
            const u32 aq = 2 * kk + (lane >> 4);
#pragma unroll
            for (int mi = 0; mi < 4; mi++) {
                const u32 row = wm * 64 + mi * 16 + (lane & 15);
                ldsm4(bA + swz(row, aq), av[mi]);
            }
            const u32 wq = 2 * kk + ((lane >> 3) & 1);
#pragma unroll
            for (int nf2 = 0; nf2 < 2; nf2++) {
                const u32 row = wn * 32 + nf2 * 16 + (lane & 7) + ((lane >> 4) << 3);
                ldsm4(bW + swz(row, wq), wv[nf2]);
            }
#pragma unroll
            for (int mi = 0; mi < 4; mi++)
#pragma unroll
                for (int nf = 0; nf < 4; nf++) {
                    const u32* W = wv[nf >> 1] + (nf & 1) * 2;
                    mma_f16(acc[mi][nf], av[mi], W[0], W[1]);
                }
        }
        if (lane == 0) mbar_arrive(sbase + 64 + (u32)(c % N_STAGE) * 8);
    }

    __syncthreads();  // mainloop done in ALL warps; ring buffers now free

    // SMEM staging areas (overlay the ring buffers)
    __half* sp = (__half*)(smem + 1024);                 // 32KB: part tile [128][128]
    float*  scp = (float*)(smem + 1024 + BUF_B);         // 16KB: c tile [128][32]
    __half* shp = (__half*)(smem + 1024 + 2 * BUF_B);    // 8KB:  h tile [128][32]
    const u32 sp_u = sb;
    const u32 sc_u = sb + BUF_B;

    // ---------------- L1A epilogue: stage part tile, coalesced store ------
    if (type == 1) {
        const bool owner = ((lane & 1) == 0);
#pragma unroll
        for (int mi = 0; mi < 4; mi++)
#pragma unroll
            for (int nf = 0; nf < 4; nf++) {
                float v0 = acc[mi][nf][0], v1 = acc[mi][nf][1];
                float v2 = acc[mi][nf][2], v3 = acc[mi][nf][3];
                const float p0 = __shfl_xor_sync(0xffffffffu, v0, 1);
                const float p1 = __shfl_xor_sync(0xffffffffu, v1, 1);
                const float p2 = __shfl_xor_sync(0xffffffffu, v2, 1);
                const float p3 = __shfl_xor_sync(0xffffffffu, v3, 1);
                if (owner) {
                    const int nl = wn * 32 + nf * 8 + 2 * (lane & 3);
                    const int rowl = wm * 64 + mi * 16 + (lane >> 2);
#pragma unroll
                    for (int rh = 0; rh < 2; rh++) {
                        const int rw2 = rowl + rh * 8;
                        __half2* d0 = (__half2*)(sp + (size_t)rw2 * 128 + nl);
                        d0[0] = __floats2half2_rn(rh ? v2 : v0, rh ? v3 : v1);
                        d0[1] = __floats2half2_rn(rh ? p2 : p0, rh ? p3 : p1);
                    }
                }
            }
        __syncthreads();
        __half* outp = g_part[step & 1];
#pragma unroll
        for (int k = 0; k < 8; k++) {
            const int idx = tid + k * 256;
            const int row = idx >> 4, q = idx & 15;
            const uint4 v = *(const uint4*)(sp + (size_t)row * 128 + q * 8);
            *(uint4*)(outp + (size_t)(m0 + row) * NCOL + u0 * 4 + q * 8) = v;
        }
        return;
    }

    // ---------------- cell epilogues (type 0: L1B, type 2: L0) ------------
    float* cmem = (type == 0) ? g_c1 : g_c0;
    const float* gb = (type == 0) ? g_b1 : g_b0;

    // stage in: c tile (and part tile for L1B), coalesced cp.async
#pragma unroll
    for (int k = 0; k < 4; k++) {
        const int idx = tid + k * 256;              // 1024 x 16B, row=idx>>3
        cp16(sc_u + (u32)idx * 16,
             cmem + (size_t)(m0 + (idx >> 3)) * H_DIM + u0 + (idx & 7) * 4);
    }
    if (type == 0) {
        const __half* pin = g_part[step & 1];
#pragma unroll
        for (int k = 0; k < 8; k++) {
            const int idx = tid + k * 256;          // 2048 x 16B, row=idx>>4
            cp16(sp_u + (u32)idx * 16,
                 pin + (size_t)(m0 + (idx >> 4)) * NCOL + u0 * 4 + (idx & 15) * 8);
        }
    }
    CP_COMMIT(); CP_WAIT0();
    __syncthreads();

    {
        const bool owner = ((lane & 1) == 0);
#pragma unroll
        for (int mi = 0; mi < 4; mi++)
#pragma unroll
            for (int nf = 0; nf < 4; nf++) {
                float v0 = acc[mi][nf][0], v1 = acc[mi][nf][1];
                float v2 = acc[mi][nf][2], v3 = acc[mi][nf][3];
                const float p0 = __shfl_xor_sync(0xffffffffu, v0, 1);
                const float p1 = __shfl_xor_sync(0xffffffffu, v1, 1);
                const float p2 = __shfl_xor_sync(0xffffffffu, v2, 1);
                const float p3 = __shfl_xor_sync(0xffffffffu, v3, 1);
                if (owner) {
                    const int nl = wn * 32 + nf * 8 + 2 * (lane & 3);
                    const int unit = nl >> 2;
                    const float4 bv = *(const float4*)(gb + u0 * 4 + nl);
                    const int rowl = wm * 64 + mi * 16 + (lane >> 2);
#pragma unroll
                    for (int rh = 0; rh < 2; rh++) {
                        const int rw2 = rowl + rh * 8;
                        float iv = (rh ? v2 : v0) + bv.x;
                        float fv = (rh ? v3 : v1) + bv.y;
                        float gv = (rh ? p2 : p0) + bv.z;
                        float ov = (rh ? p3 : p1) + bv.w;
                        if (type == 0) {
                            const __half2 e01 = *(const __half2*)(sp + (size_t)rw2 * 128 + nl);
                            const __half2 e23 = *(const __half2*)(sp + (size_t)rw2 * 128 + nl + 2);
                            iv += __low2float(e01);  fv += __high2float(e01);
                            gv += __low2float(e23);  ov += __high2float(e23);
                        }
                        const int si = rw2 * 32 + unit;
                        const float cold = scp[si];
                        const float cn = sigf(fv) * cold + sigf(iv) * tanhf_(gv);
                        const float hn = sigf(ov) * tanhf_(cn);
                        scp[si] = cn;
                        shp[si] = __float2half(hn);
                    }
                }
            }
    }
    __syncthreads();

    // coalesced writeback: h (8KB) and c (16KB)
    __half* hout = (type == 0)
        ? (g_h1all + (size_t)(step + 1) * B_DIM * H_DIM)
        : g_h0b[step & 1];
#pragma unroll
    for (int k = 0; k < 2; k++) {
        const int idx = tid + k * 256;              // 512 x 16B, row=idx>>2
        const int row = idx >> 2, q = idx & 3;
        const uint4 v = *(const uint4*)(shp + (size_t)row * 32 + q * 8);
        *(uint4*)(hout + (size_t)(m0 + row) * H_DIM + u0 + q * 8) = v;
    }
#pragma unroll
    for (int k = 0; k < 4; k++) {
        const int idx = tid + k * 256;              // 1024 x 16B, row=idx>>3
        const int row = idx >> 3, q = idx & 7;
        const uint4 v = *(const uint4*)(scp + (size_t)row * 32 + q * 4);
        *(uint4*)(cmem + (size_t)(m0 + row) * H_DIM + u0 + q * 4) = v;
    }
}

// ------------------------------------------------------------------
__global__ void prolog_k(const float* __restrict__ x,
                         const float* __restrict__ Wih0, const float* __restrict__ Whh0,
                         const float* __restrict__ Wih1, const float* __restrict__ Whh1,
                         const float* __restrict__ bih0, const float* __restrict__ bhh0,
                         const float* __restrict__ bih1, const float* __restrict__ bhh1) {
    const size_t stride = (size_t)gridDim.x * blockDim.x;
    const size_t tid0 = (size_t)blockIdx.x * blockDim.x + threadIdx.x;
    for (size_t i = tid0; i < NCOL; i += stride) {
        const size_t src = (i & 3) * H_DIM + (i >> 2);
        g_b0[i] = bih0[src] + bhh0[src];
        g_b1[i] = bih1[src] + bhh1[src];
    }
    {
        const size_t n = (size_t)4 * H_DIM * DPAD;
        for (size_t i = tid0; i < n; i += stride) {
            const size_t row = i / DPAD;
            const int k = (int)(i % DPAD);
            g_wih0[i] = __float2half((k < D_DIM) ? Wih0[row * D_DIM + k] : 0.0f);
        }
    }
    {
        const size_t n = (size_t)4 * H_DIM * H_DIM;
        for (size_t i = tid0; i < n; i += stride) {
            g_whh0[i] = __float2half(Whh0[i]);
            g_wih1[i] = __float2half(Wih1[i]);
            g_whh1[i] = __float2half(Whh1[i]);
        }
    }
    {
        const size_t n = (size_t)B_DIM * T_DIM * DPAD;
        for (size_t i = tid0; i < n; i += stride) {
            const size_t bt = i / DPAD;
            const int k = (int)(i % DPAD);
            g_x[i] = __float2half((k < D_DIM) ? x[bt * D_DIM + k] : 0.0f);
        }
    }
    {
        const size_t n = (size_t)B_DIM * H_DIM;
        for (size_t i = tid0; i < n; i += stride) {
            g_h0b[0][i] = __float2half(0.0f);
            g_h0b[1][i] = __float2half(0.0f);
            g_h1all[i] = __float2half(0.0f);   // slice 0 = h1[-1] = 0
            g_c0[i] = 0.0f; g_c1[i] = 0.0f;
        }
    }
}

__global__ void finalize_k(const float* __restrict__ Wdec,
                           const float* __restrict__ bdec, float* __restrict__ out) {
    const int b = blockIdx.x;
    const int tid = threadIdx.x;  // 128
    float p = 0.0f;
    for (int u = tid; u < H_DIM; u += 128) {
        float s = 0.0f;
        for (int t = 1; t <= T_DIM; t++)
            s += __half2float(g_h1all[((size_t)t * B_DIM + b) * H_DIM + u]);
        p += s * Wdec[u];
    }
#pragma unroll
    for (int o = 16; o; o >>= 1) p += __shfl_down_sync(0xffffffffu, p, o);
    __shared__ float red[4];
    if ((tid & 31) == 0) red[tid >> 5] = p;
    __syncthreads();
    if (tid == 0)
        out[b] = (red[0] + red[1] + red[2] + red[3]) * (1.0f / (float)T_DIM) + bdec[0];
}

// ------------------------------------------------------------------
extern "C" void kernel_launch(void* const* d_in, const int* in_sizes, int n_in,
                              void* d_out, int out_size) {
    const float* x    = (const float*)d_in[0];
    const float* Wih0 = (const float*)d_in[1];
    const float* Whh0 = (const float*)d_in[2];
    const float* bih0 = (const float*)d_in[3];
    const float* bhh0 = (const float*)d_in[4];
    const float* Wih1 = (const float*)d_in[5];
    const float* Whh1 = (const float*)d_in[6];
    const float* bih1 = (const float*)d_in[7];
    const float* bhh1 = (const float*)d_in[8];
    const float* Wdec = (const float*)d_in[9];
    const float* bdec = (const float*)d_in[10];
    float* out = (float*)d_out;

    cudaFuncSetAttribute(lstm_step, cudaFuncAttributeMaxDynamicSharedMemorySize, SMEM_TOT);

    prolog_k<<<2048, 256>>>(x, Wih0, Whh0, Wih1, Whh1, bih0, bhh0, bih1, bhh1);

    // schedule: launch(t) = { L0[t+1], L1B[t-1], L1A[t] }, 128 jobs per type
    lstm_step<<<128, 256, SMEM_TOT>>>(0, -1, -1);            // L0[0]
    lstm_step<<<256, 256, SMEM_TOT>>>(1, -1, 0);             // L0[1], L1A[0]
    for (int t = 1; t <= T_DIM - 2; ++t)                     // t = 1..126
        lstm_step<<<384, 256, SMEM_TOT>>>(t + 1, t - 1, t);
    lstm_step<<<256, 256, SMEM_TOT>>>(-1, T_DIM - 2, T_DIM - 1);
    lstm_step<<<128, 256, SMEM_TOT>>>(-1, T_DIM - 1, -1);

    finalize_k<<<B_DIM, 128>>>(Wdec, bdec, out);
}

// round 16
// speedup vs baseline: 1.6963x; 1.2332x over previous
#include <cuda_runtime.h>
#include <cuda_fp16.h>
#include <cstdint>

#define B_DIM 512
#define T_DIM 128
#define D_DIM 300
#define DPAD  320
#define H_DIM 1024
#define NCOL  4096

typedef uint32_t u32;

// ------------------------------------------------------------------
// Persistent device buffers
// ------------------------------------------------------------------
__device__ __align__(16) __half g_x[(size_t)B_DIM * T_DIM * DPAD];
__device__ __align__(16) __half g_wih0[(size_t)4 * H_DIM * DPAD];
__device__ __align__(16) __half g_whh0[(size_t)4 * H_DIM * H_DIM];
__device__ __align__(16) __half g_wih1[(size_t)4 * H_DIM * H_DIM];
__device__ __align__(16) __half g_whh1[(size_t)4 * H_DIM * H_DIM];
__device__ __align__(16) __half g_h0b[2][(size_t)B_DIM * H_DIM];
__device__ __align__(16) __half g_h1all[(size_t)(T_DIM + 1) * B_DIM * H_DIM]; // slice t+1 = h1[t]
__device__ __align__(16) float g_c0[(size_t)B_DIM * H_DIM];
__device__ __align__(16) float g_c1[(size_t)B_DIM * H_DIM];
__device__ __align__(16) float g_b0[NCOL];   // interleaved: g_b0[n] = b[(n&3)*H + (n>>2)]
__device__ __align__(16) float g_b1[NCOL];

// ------------------------------------------------------------------
// Helpers
// ------------------------------------------------------------------
__device__ __forceinline__ u32 smem_to_u32(const void* p) {
    u32 a;
    asm("{ .reg .u64 t; cvta.to.shared.u64 t, %1; cvt.u32.u64 %0, t; }" : "=r"(a) : "l"(p));
    return a;
}
__device__ __forceinline__ void cp16(u32 s, const void* g) {
    asm volatile("cp.async.cg.shared.global [%0], [%1], 16;" :: "r"(s), "l"(g));
}
#define CP_COMMIT() asm volatile("cp.async.commit_group;" ::: "memory")
#define CP_WAIT0()  asm volatile("cp.async.wait_group 0;" ::: "memory")
__device__ __forceinline__ void mbar_init(u32 mb, u32 cnt) {
    asm volatile("mbarrier.init.shared.b64 [%0], %1;" :: "r"(mb), "r"(cnt) : "memory");
}
__device__ __forceinline__ void mbar_arrive(u32 mb) {
    asm volatile("mbarrier.arrive.shared.b64 _, [%0];" :: "r"(mb) : "memory");
}
__device__ __forceinline__ void cp_arrive_noinc(u32 mb) {
    asm volatile("cp.async.mbarrier.arrive.noinc.shared.b64 [%0];" :: "r"(mb) : "memory");
}
__device__ __forceinline__ void mbar_wait(u32 mb, u32 parity) {
    u32 done;
    asm volatile("{\n\t.reg .pred p;\n\t"
        "mbarrier.try_wait.parity.acquire.cta.shared::cta.b64 p, [%1], %2;\n\t"
        "selp.b32 %0, 1, 0, p;\n\t}" : "=r"(done) : "r"(mb), "r"(parity) : "memory");
    if (!done) {
        asm volatile("{\n\t.reg .pred P1;\n\t"
            "WAIT_LOOP_%=:\n\t"
            "mbarrier.try_wait.parity.acquire.cta.shared::cta.b64 P1, [%0], %1, 0x989680;\n\t"
            "@P1 bra.uni WAIT_DONE_%=;\n\t"
            "bra.uni WAIT_LOOP_%=;\n\t"
            "WAIT_DONE_%=:\n\t}" :: "r"(mb), "r"(parity) : "memory");
    }
}
__device__ __forceinline__ void ldsm4(u32 addr, u32* r) {
    asm volatile("ldmatrix.sync.aligned.m8n8.x4.shared.b16 {%0,%1,%2,%3}, [%4];"
                 : "=r"(r[0]), "=r"(r[1]), "=r"(r[2]), "=r"(r[3]) : "r"(addr));
}
__device__ __forceinline__ void mma_f16(float* d, const u32* a, u32 b0, u32 b1) {
    asm volatile("mma.sync.aligned.m16n8k16.row.col.f32.f16.f16.f32 "
                 "{%0,%1,%2,%3}, {%4,%5,%6,%7}, {%8,%9}, {%0,%1,%2,%3};"
                 : "+f"(d[0]), "+f"(d[1]), "+f"(d[2]), "+f"(d[3])
                 : "r"(a[0]), "r"(a[1]), "r"(a[2]), "r"(a[3]), "r"(b0), "r"(b1));
}
__device__ __forceinline__ u32 swz(u32 row, u32 q) {
    return row * 128u + ((q ^ (row & 7u)) << 4);
}
__device__ __forceinline__ float sigf(float x) { return __fdividef(1.0f, 1.0f + __expf(-x)); }
__device__ __forceinline__ float tanhf_(float x) {
    return 1.0f - 2.0f * __fdividef(1.0f, 1.0f + __expf(2.0f * x));
}

#define TILE_B   16384          // 128 x 64 fp16
#define BUF_B    (2 * TILE_B)   // A, W
#define N_STAGE  3
#define SMEM_TOT (1024 + N_STAGE * BUF_B)  // 99328 -> 2 CTAs/SM

// ------------------------------------------------------------------
// Fused GEMM + LSTM-cell step kernel (one job = one 128x128 tile).
// CTA: 256 thr, 8 warps (2Mx4N), warp tile 64x32, BK=64.
// type 0 = L1 full (h0[t]@Wih1 + h1[t-1]@Whh1 -> cell1 -> g_h1all), 32 ch
// type 2 = L0      (x[t]@Wih0 + h0[t-1]@Whh0  -> cell0 -> g_h0b),   21 ch
// Epilogue I/O staged through SMEM (ring buffers dead after mainloop),
// 16B coalesced global traffic only. No partial-gates round trip.
// ------------------------------------------------------------------
__global__ void __launch_bounds__(256, 2)
lstm_step(int s_l1, int s_l0) {
    extern __shared__ __align__(16) char smem[];
    const u32 sbase = smem_to_u32(smem);
    const u32 sb = sbase + 1024;
    const int tid = threadIdx.x;
    const int lane = tid & 31;
    const int wid = tid >> 5;
    const int wm = wid >> 2;
    const int wn = wid & 3;

    // job decode: groups of 128 blocks, L1 first (longer jobs first)
    const int g = blockIdx.x >> 7;
    const int jb = blockIdx.x & 127;
    int type = 0, step = 0;
    {
        int k = 0;
        if (s_l1 >= 0) { if (g == k) { type = 0; step = s_l1; } k++; }
        if (s_l0 >= 0) { if (g == k) { type = 2; step = s_l0; } k++; }
    }
    const int u0 = (jb & 31) * 32;
    const int m0 = (jb >> 5) * 128;

    if (tid == 0) {
#pragma unroll
        for (int s = 0; s < N_STAGE; s++) {
            mbar_init(sbase + 32 + s * 8, 256);  // full: cp.async noinc arrivals
            mbar_init(sbase + 64 + s * 8, 8);    // empty: lane-0 per consumer warp
        }
    }
    __syncthreads();

    // per-thread load row
    const int r = tid >> 1;
    const int h4 = (tid & 1) * 4;
    const int wrow = (r & 3) * H_DIM + u0 + (r >> 2);

    const __half *pa0, *pw0, *pa1, *pw1;
    int nc0, NC;
    if (type == 2) {
        pa0 = g_x + (size_t)(m0 + r) * (T_DIM * DPAD) + (size_t)step * DPAD;
        pw0 = g_wih0 + (size_t)wrow * DPAD;
        nc0 = DPAD / 64;  // 5
        pa1 = g_h0b[(step - 1) & 1] + (size_t)(m0 + r) * H_DIM;
        pw1 = g_whh0 + (size_t)wrow * H_DIM;
        NC = nc0 + 16;    // 21
    } else {
        pa0 = g_h0b[step & 1] + (size_t)(m0 + r) * H_DIM;           // h0[step]
        pw0 = g_wih1 + (size_t)wrow * H_DIM;
        nc0 = 16;
        pa1 = g_h1all + ((size_t)step * B_DIM + m0 + r) * H_DIM;    // h1[step-1]
        pw1 = g_whh1 + (size_t)wrow * H_DIM;
        NC = 32;
    }

    float acc[4][4][4];
#pragma unroll
    for (int mi = 0; mi < 4; mi++)
#pragma unroll
        for (int nf = 0; nf < 4; nf++)
#pragma unroll
            for (int q = 0; q < 4; q++) acc[mi][nf][q] = 0.0f;

    auto produce = [&](int c) {
        const __half* pa; const __half* pw; int k0;
        if (c < nc0) { pa = pa0; pw = pw0; k0 = c * 64; }
        else         { pa = pa1; pw = pw1; k0 = (c - nc0) * 64; }
        const u32 d = sb + (u32)(c % N_STAGE) * BUF_B;
#pragma unroll
        for (int j = 0; j < 4; j++) {
            const int q = h4 + j;
            const u32 so = swz((u32)r, (u32)q);
            cp16(d + so, pa + k0 + q * 8);
            cp16(d + TILE_B + so, pw + k0 + q * 8);
        }
        cp_arrive_noinc(sbase + 32 + (u32)(c % N_STAGE) * 8);
    };

    produce(0);
    produce(1);

    for (int c = 0; c < NC; c++) {
        const int pc = c + 2;
        if (pc < NC) {
            if (pc >= N_STAGE)
                mbar_wait(sbase + 64 + (u32)(pc % N_STAGE) * 8,
                          (u32)(((pc / N_STAGE) - 1) & 1));
            produce(pc);
        }
        mbar_wait(sbase + 32 + (u32)(c % N_STAGE) * 8, (u32)((c / N_STAGE) & 1));

        const u32 bA = sb + (u32)(c % N_STAGE) * BUF_B;
        const u32 bW = bA + TILE_B;
#pragma unroll
        for (int kk = 0; kk < 4; kk++) {
            u32 av[4][4], wv[2][4];
            const u32 aq = 2 * kk + (lane >> 4);
#pragma unroll
            for (int mi = 0; mi < 4; mi++) {
                const u32 row = wm * 64 + mi * 16 + (lane & 15);
                ldsm4(bA + swz(row, aq), av[mi]);
            }
            const u32 wq = 2 * kk + ((lane >> 3) & 1);
#pragma unroll
            for (int nf2 = 0; nf2 < 2; nf2++) {
                const u32 row = wn * 32 + nf2 * 16 + (lane & 7) + ((lane >> 4) << 3);
                ldsm4(bW + swz(row, wq), wv[nf2]);
            }
#pragma unroll
            for (int mi = 0; mi < 4; mi++)
#pragma unroll
                for (int nf = 0; nf < 4; nf++) {
                    const u32* W = wv[nf >> 1] + (nf & 1) * 2;
                    mma_f16(acc[mi][nf], av[mi], W[0], W[1]);
                }
        }
        if (lane == 0) mbar_arrive(sbase + 64 + (u32)(c % N_STAGE) * 8);
    }

    __syncthreads();  // mainloop done in ALL warps; ring buffers now free

    // SMEM staging areas (overlay the ring buffers)
    float*  scp = (float*)(smem + 1024);                 // 16KB: c tile [128][32]
    __half* shp = (__half*)(smem + 1024 + 16384);        // 8KB:  h tile [128][32]
    const u32 sc_u = sb;

    float* cmem = (type == 0) ? g_c1 : g_c0;
    const float* gb = (type == 0) ? g_b1 : g_b0;

    // stage in: c tile, coalesced cp.async (1024 x 16B)
#pragma unroll
    for (int k = 0; k < 4; k++) {
        const int idx = tid + k * 256;
        cp16(sc_u + (u32)idx * 16,
             cmem + (size_t)(m0 + (idx >> 3)) * H_DIM + u0 + (idx & 7) * 4);
    }
    CP_COMMIT(); CP_WAIT0();
    __syncthreads();

    {
        const bool owner = ((lane & 1) == 0);
#pragma unroll
        for (int mi = 0; mi < 4; mi++)
#pragma unroll
            for (int nf = 0; nf < 4; nf++) {
                float v0 = acc[mi][nf][0], v1 = acc[mi][nf][1];
                float v2 = acc[mi][nf][2], v3 = acc[mi][nf][3];
                const float p0 = __shfl_xor_sync(0xffffffffu, v0, 1);
                const float p1 = __shfl_xor_sync(0xffffffffu, v1, 1);
                const float p2 = __shfl_xor_sync(0xffffffffu, v2, 1);
                const float p3 = __shfl_xor_sync(0xffffffffu, v3, 1);
                if (owner) {
                    const int nl = wn * 32 + nf * 8 + 2 * (lane & 3);
                    const int unit = nl >> 2;
                    const float4 bv = *(const float4*)(gb + u0 * 4 + nl);
                    const int rowl = wm * 64 + mi * 16 + (lane >> 2);
#pragma unroll
                    for (int rh = 0; rh < 2; rh++) {
                        const int rw2 = rowl + rh * 8;
                        const float iv = (rh ? v2 : v0) + bv.x;
                        const float fv = (rh ? v3 : v1) + bv.y;
                        const float gv = (rh ? p2 : p0) + bv.z;
                        const float ov = (rh ? p3 : p1) + bv.w;
                        const int si = rw2 * 32 + unit;
                        const float cold = scp[si];
                        const float cn = sigf(fv) * cold + sigf(iv) * tanhf_(gv);
                        const float hn = sigf(ov) * tanhf_(cn);
                        scp[si] = cn;
                        shp[si] = __float2half(hn);
                    }
                }
            }
    }
    __syncthreads();

    // coalesced writeback: h (8KB) and c (16KB)
    __half* hout = (type == 0)
        ? (g_h1all + (size_t)(step + 1) * B_DIM * H_DIM)
        : g_h0b[step & 1];
#pragma unroll
    for (int k = 0; k < 2; k++) {
        const int idx = tid + k * 256;
        const int row = idx >> 2, q = idx & 3;
        const uint4 v = *(const uint4*)(shp + (size_t)row * 32 + q * 8);
        *(uint4*)(hout + (size_t)(m0 + row) * H_DIM + u0 + q * 8) = v;
    }
#pragma unroll
    for (int k = 0; k < 4; k++) {
        const int idx = tid + k * 256;
        const int row = idx >> 3, q = idx & 7;
        const uint4 v = *(const uint4*)(scp + (size_t)row * 32 + q * 4);
        *(uint4*)(cmem + (size_t)(m0 + row) * H_DIM + u0 + q * 4) = v;
    }
}

// ------------------------------------------------------------------
__global__ void prolog_k(const float* __restrict__ x,
                         const float* __restrict__ Wih0, const float* __restrict__ Whh0,
                         const float* __restrict__ Wih1, const float* __restrict__ Whh1,
                         const float* __restrict__ bih0, const float* __restrict__ bhh0,
                         const float* __restrict__ bih1, const float* __restrict__ bhh1) {
    const size_t stride = (size_t)gridDim.x * blockDim.x;
    const size_t tid0 = (size_t)blockIdx.x * blockDim.x + threadIdx.x;
    for (size_t i = tid0; i < NCOL; i += stride) {
        const size_t src = (i & 3) * H_DIM + (i >> 2);
        g_b0[i] = bih0[src] + bhh0[src];
        g_b1[i] = bih1[src] + bhh1[src];
    }
    {
        const size_t n = (size_t)4 * H_DIM * DPAD;
        for (size_t i = tid0; i < n; i += stride) {
            const size_t row = i / DPAD;
            const int k = (int)(i % DPAD);
            g_wih0[i] = __float2half((k < D_DIM) ? Wih0[row * D_DIM + k] : 0.0f);
        }
    }
    {
        const size_t n = (size_t)4 * H_DIM * H_DIM;
        for (size_t i = tid0; i < n; i += stride) {
            g_whh0[i] = __float2half(Whh0[i]);
            g_wih1[i] = __float2half(Wih1[i]);
            g_whh1[i] = __float2half(Whh1[i]);
        }
    }
    {
        const size_t n = (size_t)B_DIM * T_DIM * DPAD;
        for (size_t i = tid0; i < n; i += stride) {
            const size_t bt = i / DPAD;
            const int k = (int)(i % DPAD);
            g_x[i] = __float2half((k < D_DIM) ? x[bt * D_DIM + k] : 0.0f);
        }
    }
    {
        const size_t n = (size_t)B_DIM * H_DIM;
        for (size_t i = tid0; i < n; i += stride) {
            g_h0b[0][i] = __float2half(0.0f);
            g_h0b[1][i] = __float2half(0.0f);
            g_h1all[i] = __float2half(0.0f);   // slice 0 = h1[-1] = 0
            g_c0[i] = 0.0f; g_c1[i] = 0.0f;
        }
    }
}

__global__ void finalize_k(const float* __restrict__ Wdec,
                           const float* __restrict__ bdec, float* __restrict__ out) {
    const int b = blockIdx.x;
    const int tid = threadIdx.x;  // 128
    float p = 0.0f;
    for (int u = tid; u < H_DIM; u += 128) {
        float s = 0.0f;
        for (int t = 1; t <= T_DIM; t++)
            s += __half2float(g_h1all[((size_t)t * B_DIM + b) * H_DIM + u]);
        p += s * Wdec[u];
    }
#pragma unroll
    for (int o = 16; o; o >>= 1) p += __shfl_down_sync(0xffffffffu, p, o);
    __shared__ float red[4];
    if ((tid & 31) == 0) red[tid >> 5] = p;
    __syncthreads();
    if (tid == 0)
        out[b] = (red[0] + red[1] + red[2] + red[3]) * (1.0f / (float)T_DIM) + bdec[0];
}

// ------------------------------------------------------------------
extern "C" void kernel_launch(void* const* d_in, const int* in_sizes, int n_in,
                              void* d_out, int out_size) {
    const float* x    = (const float*)d_in[0];
    const float* Wih0 = (const float*)d_in[1];
    const float* Whh0 = (const float*)d_in[2];
    const float* bih0 = (const float*)d_in[3];
    const float* bhh0 = (const float*)d_in[4];
    const float* Wih1 = (const float*)d_in[5];
    const float* Whh1 = (const float*)d_in[6];
    const float* bih1 = (const float*)d_in[7];
    const float* bhh1 = (const float*)d_in[8];
    const float* Wdec = (const float*)d_in[9];
    const float* bdec = (const float*)d_in[10];
    float* out = (float*)d_out;

    cudaFuncSetAttribute(lstm_step, cudaFuncAttributeMaxDynamicSharedMemorySize, SMEM_TOT);

    prolog_k<<<2048, 256>>>(x, Wih0, Whh0, Wih1, Whh1, bih0, bhh0, bih1, bhh1);

    // schedule: launch(r) = { L1[r-2] (32ch), L0[r] (21ch) }
    for (int rr = 0; rr < T_DIM + 2; ++rr) {
        const int s_l1 = (rr >= 2) ? (rr - 2) : -1;
        const int s_l0 = (rr <= T_DIM - 1) ? rr : -1;
        const int ngrp = (s_l1 >= 0) + (s_l0 >= 0);
        lstm_step<<<ngrp * 128, 256, SMEM_TOT>>>(s_l1, s_l0);
    }

    finalize_k<<<B_DIM, 128>>>(Wdec, bdec, out);
}

// round 17
// speedup vs baseline: 2.2634x; 1.3343x over previous
#include <cuda_runtime.h>
#include <cuda_fp16.h>
#include <cstdint>

#define B_DIM 512
#define T_DIM 128
#define D_DIM 300
#define DPAD  320
#define H_DIM 1024
#define NCOL  4096
#define BLKH  8192     // halves per 16KB chunk-block (128 rows x 64 k)

typedef uint32_t u32;

// ------------------------------------------------------------------
// Persistent device buffers — packed, pre-swizzled chunk blocks.
// Block layout (bytes): off(row, q) = row*128 + ((q ^ (row&7))<<4), q=0..7
// ------------------------------------------------------------------
__device__ __align__(16) __half g_xp[(size_t)T_DIM * 4 * 5 * BLKH];        // x[t][mt][c]
__device__ __align__(16) __half g_w0p[(size_t)32 * 5 * BLKH];              // Wih0[ut][c]
__device__ __align__(16) __half g_wh0p[(size_t)32 * 16 * BLKH];            // Whh0[ut][c]
__device__ __align__(16) __half g_w1p[(size_t)32 * 16 * BLKH];             // Wih1[ut][c]
__device__ __align__(16) __half g_wh1p[(size_t)32 * 16 * BLKH];            // Whh1[ut][c]
__device__ __align__(16) __half g_h0p[(size_t)3 * 4 * 16 * BLKH];          // h0[r%3][mt][c]
__device__ __align__(16) __half g_h1p[(size_t)(T_DIM + 1) * 4 * 16 * BLKH];// h1[t+1][mt][c]
__device__ __align__(16) float g_c0[(size_t)B_DIM * H_DIM];
__device__ __align__(16) float g_c1[(size_t)B_DIM * H_DIM];
__device__ __align__(16) float g_b0[NCOL];   // interleaved: g_b0[n] = b[(n&3)*H + (n>>2)]
__device__ __align__(16) float g_b1[NCOL];

// ------------------------------------------------------------------
// Helpers
// ------------------------------------------------------------------
__device__ __forceinline__ u32 smem_to_u32(const void* p) {
    u32 a;
    asm("{ .reg .u64 t; cvta.to.shared.u64 t, %1; cvt.u32.u64 %0, t; }" : "=r"(a) : "l"(p));
    return a;
}
__device__ __forceinline__ void cp16(u32 s, const void* g) {
    asm volatile("cp.async.cg.shared.global [%0], [%1], 16;" :: "r"(s), "l"(g));
}
#define CP_COMMIT() asm volatile("cp.async.commit_group;" ::: "memory")
#define CP_WAIT0()  asm volatile("cp.async.wait_group 0;" ::: "memory")
__device__ __forceinline__ void mbar_init(u32 mb, u32 cnt) {
    asm volatile("mbarrier.init.shared.b64 [%0], %1;" :: "r"(mb), "r"(cnt) : "memory");
}
__device__ __forceinline__ void mbar_arrive(u32 mb) {
    asm volatile("mbarrier.arrive.shared.b64 _, [%0];" :: "r"(mb) : "memory");
}
__device__ __forceinline__ void mbar_expect_tx(u32 mb, u32 bytes) {
    asm volatile("mbarrier.arrive.expect_tx.shared.b64 _, [%0], %1;"
                 :: "r"(mb), "r"(bytes) : "memory");
}
__device__ __forceinline__ void bulk_g2s(u32 dst, const void* src, u32 bytes, u32 mb) {
    asm volatile("cp.async.bulk.shared::cta.global.mbarrier::complete_tx::bytes "
                 "[%0], [%1], %2, [%3];"
                 :: "r"(dst), "l"(src), "r"(bytes), "r"(mb) : "memory");
}
__device__ __forceinline__ void mbar_wait(u32 mb, u32 parity) {
    u32 done;
    asm volatile("{\n\t.reg .pred p;\n\t"
        "mbarrier.try_wait.parity.acquire.cta.shared::cta.b64 p, [%1], %2;\n\t"
        "selp.b32 %0, 1, 0, p;\n\t}" : "=r"(done) : "r"(mb), "r"(parity) : "memory");
    if (!done) {
        asm volatile("{\n\t.reg .pred P1;\n\t"
            "WAIT_LOOP_%=:\n\t"
            "mbarrier.try_wait.parity.acquire.cta.shared::cta.b64 P1, [%0], %1, 0x989680;\n\t"
            "@P1 bra.uni WAIT_DONE_%=;\n\t"
            "bra.uni WAIT_LOOP_%=;\n\t"
            "WAIT_DONE_%=:\n\t}" :: "r"(mb), "r"(parity) : "memory");
    }
}
__device__ __forceinline__ void ldsm4(u32 addr, u32* r) {
    asm volatile("ldmatrix.sync.aligned.m8n8.x4.shared.b16 {%0,%1,%2,%3}, [%4];"
                 : "=r"(r[0]), "=r"(r[1]), "=r"(r[2]), "=r"(r[3]) : "r"(addr));
}
__device__ __forceinline__ void mma_f16(float* d, const u32* a, u32 b0, u32 b1) {
    asm volatile("mma.sync.aligned.m16n8k16.row.col.f32.f16.f16.f32 "
                 "{%0,%1,%2,%3}, {%4,%5,%6,%7}, {%8,%9}, {%0,%1,%2,%3};"
                 : "+f"(d[0]), "+f"(d[1]), "+f"(d[2]), "+f"(d[3])
                 : "r"(a[0]), "r"(a[1]), "r"(a[2]), "r"(a[3]), "r"(b0), "r"(b1));
}
__device__ __forceinline__ u32 swz(u32 row, u32 q) {
    return row * 128u + ((q ^ (row & 7u)) << 4);
}
__device__ __forceinline__ float sigf(float x) { return __fdividef(1.0f, 1.0f + __expf(-x)); }
__device__ __forceinline__ float tanhf_(float x) {
    return 1.0f - 2.0f * __fdividef(1.0f, 1.0f + __expf(2.0f * x));
}

#define TILE_B   16384          // 128 x 64 fp16 (one chunk block)
#define BUF_B    (2 * TILE_B)   // A, W
#define N_STAGE  3
#define SMEM_TOT (1024 + N_STAGE * BUF_B)  // 99328 -> 2 CTAs/SM

// ------------------------------------------------------------------
// Fused GEMM + LSTM-cell step kernel (one job = one 128x128 tile).
// CTA: 256 thr, 8 warps (2Mx4N), warp tile 64x32, BK=64.
// type 0 = L1 (h0[t]@Wih1 + h1[t-1]@Whh1 -> cell1 -> g_h1p), 32 ch
// type 2 = L0 (x[t]@Wih0 + h0[t-1]@Whh0  -> cell0 -> g_h0p), 21 ch
// Tiles arrive via cp.async.bulk of pre-swizzled 16KB blocks (1 instr each).
// h0 is triple-buffered by round%3 (no same-launch write/read aliasing).
// ------------------------------------------------------------------
__global__ void __launch_bounds__(256, 2)
lstm_step(int s_l1, int s_l0) {
    extern __shared__ __align__(16) char smem[];
    const u32 sbase = smem_to_u32(smem);
    const u32 sb = sbase + 1024;
    const int tid = threadIdx.x;
    const int lane = tid & 31;
    const int wid = tid >> 5;
    const int wm = wid >> 2;
    const int wn = wid & 3;

    // job decode: groups of 128 blocks, L1 first (longer jobs first)
    const int g = blockIdx.x >> 7;
    const int jb = blockIdx.x & 127;
    int type = 0, step = 0;
    {
        int k = 0;
        if (s_l1 >= 0) { if (g == k) { type = 0; step = s_l1; } k++; }
        if (s_l0 >= 0) { if (g == k) { type = 2; step = s_l0; } k++; }
    }
    const int ut = jb & 31;           // unit tile index (32 units each)
    const int mt = jb >> 5;           // m tile index (128 batches each)
    const int u0 = ut * 32;
    const int m0 = mt * 128;

    if (tid == 0) {
#pragma unroll
        for (int s = 0; s < N_STAGE; s++) {
            mbar_init(sbase + 32 + s * 8, 1);    // full: expect_tx pattern
            mbar_init(sbase + 64 + s * 8, 8);    // empty: lane-0 per warp
        }
    }
    __syncthreads();

    // block-base pointers (chunk blocks of BLKH halves)
    const __half *pa0, *pw0, *pa1, *pw1;
    int nc0, NC;
    if (type == 2) {
        pa0 = g_xp + ((size_t)step * 4 + mt) * 5 * BLKH;
        pw0 = g_w0p + (size_t)ut * 5 * BLKH;
        nc0 = 5;
        pa1 = g_h0p + ((size_t)((step + 2) % 3) * 4 + mt) * 16 * BLKH;  // h0[step-1]
        pw1 = g_wh0p + (size_t)ut * 16 * BLKH;
        NC = 21;
    } else {
        pa0 = g_h0p + ((size_t)(step % 3) * 4 + mt) * 16 * BLKH;        // h0[step]
        pw0 = g_w1p + (size_t)ut * 16 * BLKH;
        nc0 = 16;
        pa1 = g_h1p + ((size_t)step * 4 + mt) * 16 * BLKH;              // h1[step-1]
        pw1 = g_wh1p + (size_t)ut * 16 * BLKH;
        NC = 32;
    }

    float acc[4][4][4];
#pragma unroll
    for (int mi = 0; mi < 4; mi++)
#pragma unroll
        for (int nf = 0; nf < 4; nf++)
#pragma unroll
            for (int q = 0; q < 4; q++) acc[mi][nf][q] = 0.0f;

    // producer (tid 0 only): one expect_tx + two 16KB bulk copies per chunk
    auto produce = [&](int c) {
        const __half* pa; const __half* pw; int cl;
        if (c < nc0) { pa = pa0; pw = pw0; cl = c; }
        else         { pa = pa1; pw = pw1; cl = c - nc0; }
        const u32 d = sb + (u32)(c % N_STAGE) * BUF_B;
        const u32 fb = sbase + 32 + (u32)(c % N_STAGE) * 8;
        mbar_expect_tx(fb, 2 * TILE_B);
        bulk_g2s(d, pa + (size_t)cl * BLKH, TILE_B, fb);
        bulk_g2s(d + TILE_B, pw + (size_t)cl * BLKH, TILE_B, fb);
    };

    if (tid == 0) { produce(0); produce(1); }

    for (int c = 0; c < NC; c++) {
        const int pc = c + 2;
        if (tid == 0 && pc < NC) {
            if (pc >= N_STAGE)
                mbar_wait(sbase + 64 + (u32)(pc % N_STAGE) * 8,
                          (u32)(((pc / N_STAGE) - 1) & 1));
            produce(pc);
        }
        mbar_wait(sbase + 32 + (u32)(c % N_STAGE) * 8, (u32)((c / N_STAGE) & 1));

        const u32 bA = sb + (u32)(c % N_STAGE) * BUF_B;
        const u32 bW = bA + TILE_B;
#pragma unroll
        for (int kk = 0; kk < 4; kk++) {
            u32 av[4][4], wv[2][4];
            const u32 aq = 2 * kk + (lane >> 4);
#pragma unroll
            for (int mi = 0; mi < 4; mi++) {
                const u32 row = wm * 64 + mi * 16 + (lane & 15);
                ldsm4(bA + swz(row, aq), av[mi]);
            }
            const u32 wq = 2 * kk + ((lane >> 3) & 1);
#pragma unroll
            for (int nf2 = 0; nf2 < 2; nf2++) {
                const u32 row = wn * 32 + nf2 * 16 + (lane & 7) + ((lane >> 4) << 3);
                ldsm4(bW + swz(row, wq), wv[nf2]);
            }
#pragma unroll
            for (int mi = 0; mi < 4; mi++)
#pragma unroll
                for (int nf = 0; nf < 4; nf++) {
                    const u32* W = wv[nf >> 1] + (nf & 1) * 2;
                    mma_f16(acc[mi][nf], av[mi], W[0], W[1]);
                }
        }
        if (lane == 0) mbar_arrive(sbase + 64 + (u32)(c % N_STAGE) * 8);
    }

    __syncthreads();  // mainloop done in ALL warps; ring buffers now free

    // SMEM staging areas (overlay the ring buffers)
    float*  scp = (float*)(smem + 1024);                 // 16KB: c tile [128][32]
    __half* shp = (__half*)(smem + 1024 + 16384);        // 8KB:  h tile [128][32]
    const u32 sc_u = sb;

    float* cmem = (type == 0) ? g_c1 : g_c0;
    const float* gb = (type == 0) ? g_b1 : g_b0;

    // stage in: c tile, coalesced cp.async (1024 x 16B)
#pragma unroll
    for (int k = 0; k < 4; k++) {
        const int idx = tid + k * 256;
        cp16(sc_u + (u32)idx * 16,
             cmem + (size_t)(m0 + (idx >> 3)) * H_DIM + u0 + (idx & 7) * 4);
    }
    CP_COMMIT(); CP_WAIT0();
    __syncthreads();

    {
        const bool owner = ((lane & 1) == 0);
#pragma unroll
        for (int mi = 0; mi < 4; mi++)
#pragma unroll
            for (int nf = 0; nf < 4; nf++) {
                float v0 = acc[mi][nf][0], v1 = acc[mi][nf][1];
                float v2 = acc[mi][nf][2], v3 = acc[mi][nf][3];
                const float p0 = __shfl_xor_sync(0xffffffffu, v0, 1);
                const float p1 = __shfl_xor_sync(0xffffffffu, v1, 1);
                const float p2 = __shfl_xor_sync(0xffffffffu, v2, 1);
                const float p3 = __shfl_xor_sync(0xffffffffu, v3, 1);
                if (owner) {
                    const int nl = wn * 32 + nf * 8 + 2 * (lane & 3);
                    const int unit = nl >> 2;
                    const float4 bv = *(const float4*)(gb + u0 * 4 + nl);
                    const int rowl = wm * 64 + mi * 16 + (lane >> 2);
#pragma unroll
                    for (int rh = 0; rh < 2; rh++) {
                        const int rw2 = rowl + rh * 8;
                        const float iv = (rh ? v2 : v0) + bv.x;
                        const float fv = (rh ? v3 : v1) + bv.y;
                        const float gv = (rh ? p2 : p0) + bv.z;
                        const float ov = (rh ? p3 : p1) + bv.w;
                        const int si = rw2 * 32 + unit;
                        const float cold = scp[si];
                        const float cn = sigf(fv) * cold + sigf(iv) * tanhf_(gv);
                        const float hn = sigf(ov) * tanhf_(cn);
                        scp[si] = cn;
                        shp[si] = __float2half(hn);
                    }
                }
            }
    }
    __syncthreads();

    // writeback h into PACKED swizzled block (512 x 16B), c to [b][H] (1024 x 16B)
    __half* hblk = (type == 0)
        ? (g_h1p + ((size_t)(step + 1) * 4 + mt) * 16 * BLKH + (size_t)(u0 >> 6) * BLKH)
        : (g_h0p + ((size_t)(step % 3) * 4 + mt) * 16 * BLKH + (size_t)(u0 >> 6) * BLKH);
    const u32 qb = (u32)((u0 & 63) >> 3);   // 0 or 4
#pragma unroll
    for (int k = 0; k < 2; k++) {
        const int idx = tid + k * 256;
        const u32 row = (u32)(idx >> 2), lq = (u32)(idx & 3);
        const uint4 v = *(const uint4*)(shp + (size_t)row * 32 + lq * 8);
        *(uint4*)((char*)hblk + swz(row, qb + lq)) = v;
    }
#pragma unroll
    for (int k = 0; k < 4; k++) {
        const int idx = tid + k * 256;
        const int row = idx >> 3, q = idx & 7;
        const uint4 v = *(const uint4*)(scp + (size_t)row * 32 + q * 4);
        *(uint4*)(cmem + (size_t)(m0 + row) * H_DIM + u0 + q * 4) = v;
    }
}

// ------------------------------------------------------------------
// Prologue: pack weights/x into swizzled chunk blocks; zero states.
// ------------------------------------------------------------------
__global__ void prolog_k(const float* __restrict__ x,
                         const float* __restrict__ Wih0, const float* __restrict__ Whh0,
                         const float* __restrict__ Wih1, const float* __restrict__ Whh1,
                         const float* __restrict__ bih0, const float* __restrict__ bhh0,
                         const float* __restrict__ bih1, const float* __restrict__ bhh1) {
    const size_t stride = (size_t)gridDim.x * blockDim.x;
    const size_t tid0 = (size_t)blockIdx.x * blockDim.x + threadIdx.x;

    for (size_t i = tid0; i < NCOL; i += stride) {
        const size_t src = (i & 3) * H_DIM + (i >> 2);
        g_b0[i] = bih0[src] + bhh0[src];
        g_b1[i] = bih1[src] + bhh1[src];
    }

    // pack Wih0 [ut][c<5]: granule = (ut, c, r, q): 32*5*128*8 = 163840
    for (size_t i = tid0; i < 163840; i += stride) {
        const u32 q = (u32)(i & 7), r = (u32)((i >> 3) & 127);
        const int c = (int)((i >> 10) % 5), ut = (int)(i / (5 * 1024));
        const int wrow = (int)(r & 3) * H_DIM + ut * 32 + (int)(r >> 2);
        __half tmp[8];
#pragma unroll
        for (int j = 0; j < 8; j++) {
            const int k = c * 64 + (int)q * 8 + j;
            tmp[j] = __float2half((k < D_DIM) ? Wih0[(size_t)wrow * D_DIM + k] : 0.0f);
        }
        *(uint4*)((char*)(g_w0p + (size_t)(ut * 5 + c) * BLKH) + swz(r, q)) = *(uint4*)tmp;
    }
    // pack Whh0/Wih1/Whh1 [ut][c<16]: granules 32*16*128*8 = 524288 each
    for (size_t i = tid0; i < 3 * 524288; i += stride) {
        const int sel = (int)(i / 524288);
        const size_t ii = i % 524288;
        const u32 q = (u32)(ii & 7), r = (u32)((ii >> 3) & 127);
        const int c = (int)((ii >> 10) & 15), ut = (int)(ii / (16 * 1024));
        const int wrow = (int)(r & 3) * H_DIM + ut * 32 + (int)(r >> 2);
        const float* W = (sel == 0) ? Whh0 : (sel == 1) ? Wih1 : Whh1;
        __half* dstb = ((sel == 0) ? g_wh0p : (sel == 1) ? g_w1p : g_wh1p)
                       + (size_t)(ut * 16 + c) * BLKH;
        __half tmp[8];
#pragma unroll
        for (int j = 0; j < 8; j++) {
            const int k = c * 64 + (int)q * 8 + j;
            tmp[j] = __float2half(W[(size_t)wrow * H_DIM + k]);
        }
        *(uint4*)((char*)dstb + swz(r, q)) = *(uint4*)tmp;
    }
    // pack x [t][mt][c<5]: granules 128*4*5*128*8 = 2621440
    for (size_t i = tid0; i < 2621440; i += stride) {
        const u32 q = (u32)(i & 7), r = (u32)((i >> 3) & 127);
        const int c = (int)((i >> 10) % 5);
        const size_t tm = i / (5 * 1024);
        const int mt = (int)(tm & 3), t = (int)(tm >> 2);
        const int b = mt * 128 + (int)r;
        __half tmp[8];
#pragma unroll
        for (int j = 0; j < 8; j++) {
            const int k = c * 64 + (int)q * 8 + j;
            tmp[j] = __float2half((k < D_DIM)
                ? x[((size_t)b * T_DIM + t) * D_DIM + k] : 0.0f);
        }
        *(uint4*)((char*)(g_xp + ((size_t)t * 4 + mt) * 5 * BLKH + (size_t)c * BLKH)
                  + swz(r, q)) = *(uint4*)tmp;
    }
    // zero h0p (all 3 slices), h1p slice 0, c states
    {
        const size_t n0 = (size_t)3 * 4 * 16 * BLKH;
        for (size_t i = tid0; i < n0; i += stride) g_h0p[i] = __float2half(0.0f);
        const size_t n1 = (size_t)4 * 16 * BLKH;
        for (size_t i = tid0; i < n1; i += stride) g_h1p[i] = __float2half(0.0f);
        const size_t nc = (size_t)B_DIM * H_DIM;
        for (size_t i = tid0; i < nc; i += stride) { g_c0[i] = 0.0f; g_c1[i] = 0.0f; }
    }
}

// ------------------------------------------------------------------
__global__ void finalize_k(const float* __restrict__ Wdec,
                           const float* __restrict__ bdec, float* __restrict__ out) {
    const int b = blockIdx.x;
    const int tid = threadIdx.x;  // 128
    const int mt = b >> 7;
    const u32 row = (u32)(b & 127);
    float p = 0.0f;
    for (int u = tid; u < H_DIM; u += 128) {
        const int cq = u >> 6;
        const u32 q = (u32)((u & 63) >> 3);
        const size_t inblk = (size_t)(swz(row, q) >> 1) + (u & 7);
        float s = 0.0f;
        for (int t = 1; t <= T_DIM; t++)
            s += __half2float(g_h1p[((size_t)t * 4 + mt) * 16 * BLKH
                                    + (size_t)cq * BLKH + inblk]);
        p += s * Wdec[u];
    }
#pragma unroll
    for (int o = 16; o; o >>= 1) p += __shfl_down_sync(0xffffffffu, p, o);
    __shared__ float red[4];
    if ((tid & 31) == 0) red[tid >> 5] = p;
    __syncthreads();
    if (tid == 0)
        out[b] = (red[0] + red[1] + red[2] + red[3]) * (1.0f / (float)T_DIM) + bdec[0];
}

// ------------------------------------------------------------------
extern "C" void kernel_launch(void* const* d_in, const int* in_sizes, int n_in,
                              void* d_out, int out_size) {
    const float* x    = (const float*)d_in[0];
    const float* Wih0 = (const float*)d_in[1];
    const float* Whh0 = (const float*)d_in[2];
    const float* bih0 = (const float*)d_in[3];
    const float* bhh0 = (const float*)d_in[4];
    const float* Wih1 = (const float*)d_in[5];
    const float* Whh1 = (const float*)d_in[6];
    const float* bih1 = (const float*)d_in[7];
    const float* bhh1 = (const float*)d_in[8];
    const float* Wdec = (const float*)d_in[9];
    const float* bdec = (const float*)d_in[10];
    float* out = (float*)d_out;

    cudaFuncSetAttribute(lstm_step, cudaFuncAttributeMaxDynamicSharedMemorySize, SMEM_TOT);

    prolog_k<<<2048, 256>>>(x, Wih0, Whh0, Wih1, Whh1, bih0, bhh0, bih1, bhh1);

    // schedule: launch(r) = { L1[r-2] (32ch), L0[r] (21ch) }
    for (int rr = 0; rr < T_DIM + 2; ++rr) {
        const int s_l1 = (rr >= 2) ? (rr - 2) : -1;
        const int s_l0 = (rr <= T_DIM - 1) ? rr : -1;
        const int ngrp = (s_l1 >= 0) + (s_l0 >= 0);
        lstm_step<<<ngrp * 128, 256, SMEM_TOT>>>(s_l1, s_l0);
    }

    finalize_k<<<B_DIM, 128>>>(Wdec, bdec, out);
}